// round 2
// baseline (speedup 1.0000x reference)
#include <cuda_runtime.h>
#include <math.h>

#define BB 8
#define NN 16384
#define KK 128
#define CC 128
#define LL 4
#define NSPLIT 64
#define XPART (NN / NSPLIT)   // 256

// ---------------- scratch (global device arrays; no allocation) ----------------
__device__ float g_bases_c[BB * NN * KK];           // 64 MB
__device__ float g_bases_s[BB * NN * KK];           // 64 MB
__device__ float g_h[BB * CC * NN];                 // 64 MB
__device__ float g_h2[BB * CC * NN];                // 64 MB
__device__ float g_pc[NSPLIT * BB * CC * KK];       // 33.5 MB
__device__ float g_ps[NSPLIT * BB * CC * KK];       // 33.5 MB
__device__ float g_xc[BB * CC * KK];
__device__ float g_xs[BB * CC * KK];
__device__ float g_x0v[BB * CC];
__device__ float g_f0v[BB * CC];
__device__ float g_fc[BB * CC * KK];
__device__ float g_fs[BB * CC * KK];

__device__ __forceinline__ float gelu_exact(float v) {
    return 0.5f * v * (1.0f + erff(v * 0.70710678118654752f));
}

// ---------------- bases: cos/sin(nodes . modes) * mask ----------------
__global__ void bases_kernel(const float* __restrict__ nodes,
                             const float* __restrict__ mask,
                             const float* __restrict__ modes) {
    int gid = blockIdx.x * blockDim.x + threadIdx.x;   // over BB*NN*KK, k fastest
    int k = gid & (KK - 1);
    int bn = gid >> 7;                                  // b*NN + n
    float n0 = nodes[bn * 2 + 0], n1 = nodes[bn * 2 + 1];
    float m = mask[bn];
    float t = n0 * modes[k * 2 + 0] + n1 * modes[k * 2 + 1];
    float s, c;
    sincosf(t, &s, &c);
    g_bases_c[gid] = c * m;
    g_bases_s[gid] = s * m;
}

// ---------------- fc0: h[b][c][n] = x[b,n,:] @ fc0_w + b ----------------
__global__ void fc0_kernel(const float* __restrict__ x,
                           const float* __restrict__ w,
                           const float* __restrict__ bias) {
    int gid = blockIdx.x * blockDim.x + threadIdx.x;   // over BB*CC*NN, n fastest
    int n = gid & (NN - 1);
    int c = (gid >> 14) & (CC - 1);
    int b = gid >> 21;
    const float* xp = x + (b * NN + n) * 3;
    float v = bias[c] + xp[0] * w[c] + xp[1] * w[CC + c] + xp[2] * w[2 * CC + c];
    g_h[gid] = v;
}

// ---------------- forward projection (split-K GEMM) ----------------
// partial_c[split,b,i,k] = sum_{x in split} h[b,i,x] * bases_c[b,x,k] * nw[b,x]
__global__ __launch_bounds__(256, 1) void fwd_kernel(const float* __restrict__ h,
                                                     const float* __restrict__ nw) {
    __shared__ float Hst[32][128];   // [xx][i]
    __shared__ float Bc[32][128];    // [xx][k]
    __shared__ float Bss[32][128];   // [xx][k]
    int split = blockIdx.x, b = blockIdx.y;
    int tid = threadIdx.x;
    int tx = tid & 15, ty = tid >> 4;
    int i0 = ty * 8, k0 = tx * 8;
    const float* hb = h + (b * CC) * NN;
    const float* bcb = g_bases_c + (b * NN) * KK;
    const float* bsb = g_bases_s + (b * NN) * KK;
    const float* nwb = nw + b * NN;
    float aC[8][8], aS[8][8];
#pragma unroll
    for (int m = 0; m < 8; m++)
#pragma unroll
        for (int n = 0; n < 8; n++) { aC[m][n] = 0.f; aS[m][n] = 0.f; }

    int xbase = split * XPART;
    for (int xc = 0; xc < XPART; xc += 32) {
        int x0 = xbase + xc;
        // h tile: [128 i][32 x] -> transposed into Hst[xx][i]
#pragma unroll
        for (int j = 0; j < 4; j++) {
            int idx = tid + j * 256;
            int row = idx >> 3, c4 = (idx & 7) << 2;   // row=i, c4=x offset
            float4 v = *(const float4*)(hb + row * NN + x0 + c4);
            Hst[c4 + 0][row] = v.x;
            Hst[c4 + 1][row] = v.y;
            Hst[c4 + 2][row] = v.z;
            Hst[c4 + 3][row] = v.w;
        }
        // bases tiles: [32 x][128 k], weighted by nw
#pragma unroll
        for (int j = 0; j < 4; j++) {
            int idx = tid + j * 256;
            int row = idx >> 5, c4 = (idx & 31) << 2;  // row=x offset, c4=k offset
            float wgt = nwb[x0 + row];
            float4 v = *(const float4*)(bcb + (x0 + row) * KK + c4);
            v.x *= wgt; v.y *= wgt; v.z *= wgt; v.w *= wgt;
            *(float4*)&Bc[row][c4] = v;
            float4 u = *(const float4*)(bsb + (x0 + row) * KK + c4);
            u.x *= wgt; u.y *= wgt; u.z *= wgt; u.w *= wgt;
            *(float4*)&Bss[row][c4] = u;
        }
        __syncthreads();
#pragma unroll 4
        for (int xx = 0; xx < 32; xx++) {
            float4 a0 = *(float4*)&Hst[xx][i0];
            float4 a1 = *(float4*)&Hst[xx][i0 + 4];
            float4 c0 = *(float4*)&Bc[xx][k0];
            float4 c1 = *(float4*)&Bc[xx][k0 + 4];
            float4 s0 = *(float4*)&Bss[xx][k0];
            float4 s1 = *(float4*)&Bss[xx][k0 + 4];
            float av[8] = {a0.x, a0.y, a0.z, a0.w, a1.x, a1.y, a1.z, a1.w};
            float cv[8] = {c0.x, c0.y, c0.z, c0.w, c1.x, c1.y, c1.z, c1.w};
            float sv[8] = {s0.x, s0.y, s0.z, s0.w, s1.x, s1.y, s1.z, s1.w};
#pragma unroll
            for (int m = 0; m < 8; m++)
#pragma unroll
                for (int n = 0; n < 8; n++) {
                    aC[m][n] += av[m] * cv[n];
                    aS[m][n] += av[m] * sv[n];
                }
        }
        __syncthreads();
    }
    float* pc = g_pc + ((split * BB + b) * CC) * KK;
    float* ps = g_ps + ((split * BB + b) * CC) * KK;
#pragma unroll
    for (int m = 0; m < 8; m++) {
        int off = (i0 + m) * KK + k0;
        *(float4*)&pc[off] = make_float4(aC[m][0], aC[m][1], aC[m][2], aC[m][3]);
        *(float4*)&pc[off + 4] = make_float4(aC[m][4], aC[m][5], aC[m][6], aC[m][7]);
        *(float4*)&ps[off] = make_float4(aS[m][0], aS[m][1], aS[m][2], aS[m][3]);
        *(float4*)&ps[off + 4] = make_float4(aS[m][4], aS[m][5], aS[m][6], aS[m][7]);
    }
}

// ---------------- reduce partials -> x_c_hat, x_s_hat(-) ----------------
__global__ void reduce_kernel() {
    int gid = blockIdx.x * blockDim.x + threadIdx.x;   // BB*CC*KK
    float sc = 0.f, ss = 0.f;
#pragma unroll
    for (int s = 0; s < NSPLIT; s++) {
        sc += g_pc[s * BB * CC * KK + gid];
        ss += g_ps[s * BB * CC * KK + gid];
    }
    g_xc[gid] = sc;
    g_xs[gid] = -ss;   // reference: x_s_hat = -einsum(...)
}

// ---------------- x_0_hat[b,i] = sum_x h * nw * mask ----------------
__global__ void x0_kernel(const float* __restrict__ h,
                          const float* __restrict__ nw,
                          const float* __restrict__ mask) {
    int i = blockIdx.x, b = blockIdx.y;
    const float* hr = h + (b * CC + i) * NN;
    const float* nwb = nw + b * NN;
    const float* mb = mask + b * NN;
    float acc = 0.f;
    for (int x = threadIdx.x; x < NN; x += 256)
        acc += hr[x] * nwb[x] * mb[x];
    __shared__ float red[256];
    red[threadIdx.x] = acc;
    __syncthreads();
    for (int s = 128; s > 0; s >>= 1) {
        if (threadIdx.x < s) red[threadIdx.x] += red[threadIdx.x + s];
        __syncthreads();
    }
    if (threadIdx.x == 0) g_x0v[b * CC + i] = red[0];
}

// ---------------- f_0_hat[b,o] = sum_i x_0[b,i] * w0[l,i,o] ----------------
__global__ void f0_kernel(const float* __restrict__ w0, int l) {
    int b = blockIdx.x, o = threadIdx.x;
    __shared__ float xs[CC];
    xs[o] = g_x0v[b * CC + o];
    __syncthreads();
    const float* w = w0 + l * CC * CC;
    float acc = 0.f;
#pragma unroll 8
    for (int i = 0; i < CC; i++) acc += xs[i] * w[i * CC + o];
    g_f0v[b * CC + o] = acc;
}

// ---------------- complex weight mixing (k-contiguous, coalesced) ----------------
__global__ void mix_kernel(const float* __restrict__ wc,
                           const float* __restrict__ ws, int l) {
    int o = blockIdx.x, b = blockIdx.y, k = threadIdx.x;
    const float* wcl = wc + l * CC * CC * KK;
    const float* wsl = ws + l * CC * CC * KK;
    float fcA = 0.f, fsA = 0.f;
#pragma unroll 4
    for (int i = 0; i < CC; i++) {
        float xc = g_xc[(b * CC + i) * KK + k];
        float xsv = g_xs[(b * CC + i) * KK + k];
        float wcv = wcl[(i * CC + o) * KK + k];
        float wsv = wsl[(i * CC + o) * KK + k];
        fcA += xc * wcv - xsv * wsv;
        fsA += xsv * wcv + xc * wsv;
    }
    g_fc[(b * CC + o) * KK + k] = fcA;
    g_fs[(b * CC + o) * KK + k] = fsA;
}

// ---------------- inverse projection + conv + bias + f0*mask + gelu ----------------
// hout[b,o,x] = 2*fc@bases_c^T - 2*fs@bases_s^T + conv_w@h + conv_b + f0*mask, opt gelu
__global__ __launch_bounds__(256, 2) void inv_kernel(const float* __restrict__ hin,
                                                     float* __restrict__ hout,
                                                     const float* __restrict__ convw,
                                                     const float* __restrict__ convb,
                                                     const float* __restrict__ mask,
                                                     int l, int apply_gelu) {
    __shared__ float Ast[32][128];   // [cc][o]
    __shared__ float Bs[32][128];    // [cc][x]
    int x0 = blockIdx.x * 128, b = blockIdx.y;
    int tid = threadIdx.x;
    int tx = tid & 15, ty = tid >> 4;
    int o0 = ty * 8, xf0 = tx * 8;
    float acc[8][8];
#pragma unroll
    for (int m = 0; m < 8; m++)
#pragma unroll
        for (int n = 0; n < 8; n++) acc[m][n] = 0.f;

    for (int pass = 0; pass < 3; pass++) {
        const float* A;
        const float* Bsrc;
        float scale;
        if (pass == 0)      { A = g_fc + (b * CC) * KK; Bsrc = g_bases_c + (b * NN) * KK; scale = 2.f; }
        else if (pass == 1) { A = g_fs + (b * CC) * KK; Bsrc = g_bases_s + (b * NN) * KK; scale = -2.f; }
        else                { A = convw + l * CC * CC;  Bsrc = hin + (b * CC) * NN;       scale = 1.f; }

        for (int c0 = 0; c0 < 128; c0 += 32) {
            // A tile: source [o][contr] -> Ast[cc][o]
#pragma unroll
            for (int j = 0; j < 4; j++) {
                int idx = tid + j * 256;
                int row = idx >> 3, c4 = (idx & 7) << 2;   // row=o, c4=contr offset
                float4 v = *(const float4*)(A + row * 128 + c0 + c4);
                Ast[c4 + 0][row] = v.x * scale;
                Ast[c4 + 1][row] = v.y * scale;
                Ast[c4 + 2][row] = v.z * scale;
                Ast[c4 + 3][row] = v.w * scale;
            }
            if (pass < 2) {
                // bases [x][k]: transpose into Bs[kk][x]
#pragma unroll
                for (int j = 0; j < 4; j++) {
                    int idx = tid + j * 256;
                    int row = idx >> 3, c4 = (idx & 7) << 2;  // row=x offset, c4=k offset
                    float4 v = *(const float4*)(Bsrc + (x0 + row) * KK + c0 + c4);
                    Bs[c4 + 0][row] = v.x;
                    Bs[c4 + 1][row] = v.y;
                    Bs[c4 + 2][row] = v.z;
                    Bs[c4 + 3][row] = v.w;
                }
            } else {
                // h [i][x]: direct
#pragma unroll
                for (int j = 0; j < 4; j++) {
                    int idx = tid + j * 256;
                    int row = idx >> 5, c4 = (idx & 31) << 2;  // row=i offset, c4=x offset
                    *(float4*)&Bs[row][c4] = *(const float4*)(Bsrc + (c0 + row) * NN + x0 + c4);
                }
            }
            __syncthreads();
#pragma unroll 4
            for (int cc = 0; cc < 32; cc++) {
                float4 a0 = *(float4*)&Ast[cc][o0];
                float4 a1 = *(float4*)&Ast[cc][o0 + 4];
                float4 b0 = *(float4*)&Bs[cc][xf0];
                float4 b1 = *(float4*)&Bs[cc][xf0 + 4];
                float av[8] = {a0.x, a0.y, a0.z, a0.w, a1.x, a1.y, a1.z, a1.w};
                float bv[8] = {b0.x, b0.y, b0.z, b0.w, b1.x, b1.y, b1.z, b1.w};
#pragma unroll
                for (int m = 0; m < 8; m++)
#pragma unroll
                    for (int n = 0; n < 8; n++) acc[m][n] += av[m] * bv[n];
            }
            __syncthreads();
        }
    }
    // epilogue
    const float* mb = mask + b * NN + x0 + xf0;
#pragma unroll
    for (int m = 0; m < 8; m++) {
        int o = o0 + m;
        float f0v = g_f0v[b * CC + o];
        float cb = convb[l * CC + o];
        float* outp = hout + (b * CC + o) * NN + x0 + xf0;
#pragma unroll
        for (int n = 0; n < 8; n++) {
            float v = acc[m][n] + f0v * mb[n] + cb;
            if (apply_gelu) v = gelu_exact(v);
            outp[n] = v;
        }
    }
}

// ---------------- fc1: hout[b,j,x] = gelu(sum_c h[b,c,x]*fc1_w[c,j] + b1[j]) ----------------
__global__ __launch_bounds__(256, 2) void fc1_kernel(const float* __restrict__ hin,
                                                     float* __restrict__ hout,
                                                     const float* __restrict__ w1,
                                                     const float* __restrict__ b1) {
    __shared__ float Ast[32][128];   // [cc][j]  (fc1_w is [c][j]: direct copy)
    __shared__ float Bs[32][128];    // [cc][x]
    int x0 = blockIdx.x * 128, b = blockIdx.y;
    int tid = threadIdx.x;
    int tx = tid & 15, ty = tid >> 4;
    int o0 = ty * 8, xf0 = tx * 8;
    float acc[8][8];
#pragma unroll
    for (int m = 0; m < 8; m++)
#pragma unroll
        for (int n = 0; n < 8; n++) acc[m][n] = 0.f;

    for (int c0 = 0; c0 < 128; c0 += 32) {
#pragma unroll
        for (int j = 0; j < 4; j++) {
            int idx = tid + j * 256;
            int row = idx >> 5, c4 = (idx & 31) << 2;   // row=c offset, c4=j offset
            *(float4*)&Ast[row][c4] = *(const float4*)(w1 + (c0 + row) * 128 + c4);
        }
#pragma unroll
        for (int j = 0; j < 4; j++) {
            int idx = tid + j * 256;
            int row = idx >> 5, c4 = (idx & 31) << 2;
            *(float4*)&Bs[row][c4] = *(const float4*)(hin + (b * CC + c0 + row) * NN + x0 + c4);
        }
        __syncthreads();
#pragma unroll 4
        for (int cc = 0; cc < 32; cc++) {
            float4 a0 = *(float4*)&Ast[cc][o0];
            float4 a1 = *(float4*)&Ast[cc][o0 + 4];
            float4 b0 = *(float4*)&Bs[cc][xf0];
            float4 b1v = *(float4*)&Bs[cc][xf0 + 4];
            float av[8] = {a0.x, a0.y, a0.z, a0.w, a1.x, a1.y, a1.z, a1.w};
            float bv[8] = {b0.x, b0.y, b0.z, b0.w, b1v.x, b1v.y, b1v.z, b1v.w};
#pragma unroll
            for (int m = 0; m < 8; m++)
#pragma unroll
                for (int n = 0; n < 8; n++) acc[m][n] += av[m] * bv[n];
        }
        __syncthreads();
    }
#pragma unroll
    for (int m = 0; m < 8; m++) {
        int jj = o0 + m;
        float bj = b1[jj];
        float* outp = hout + (b * CC + jj) * NN + x0 + xf0;
#pragma unroll
        for (int n = 0; n < 8; n++) outp[n] = gelu_exact(acc[m][n] + bj);
    }
}

// ---------------- fc2 + mask ----------------
__global__ void fc2_kernel(const float* __restrict__ hin,
                           float* __restrict__ out,
                           const float* __restrict__ w2,
                           const float* __restrict__ b2,
                           const float* __restrict__ mask) {
    __shared__ float ws[128];
    int x0 = blockIdx.x * 128, b = blockIdx.y;
    ws[threadIdx.x] = w2[threadIdx.x];
    __syncthreads();
    int x = x0 + threadIdx.x;
    float acc = 0.f;
#pragma unroll 8
    for (int j = 0; j < 128; j++) acc += hin[(b * CC + j) * NN + x] * ws[j];
    out[b * NN + x] = (acc + b2[0]) * mask[b * NN + x];
}

// ---------------- launch ----------------
extern "C" void kernel_launch(void* const* d_in, const int* in_sizes, int n_in,
                              void* d_out, int out_size) {
    const float* x     = (const float*)d_in[0];
    const float* nodes = (const float*)d_in[1];
    const float* mask  = (const float*)d_in[2];
    const float* nw    = (const float*)d_in[3];
    const float* modes = (const float*)d_in[4];
    const float* fc0w  = (const float*)d_in[5];
    const float* fc0b  = (const float*)d_in[6];
    const float* wc    = (const float*)d_in[7];
    const float* ws_   = (const float*)d_in[8];
    const float* w0    = (const float*)d_in[9];
    const float* convw = (const float*)d_in[10];
    const float* convb = (const float*)d_in[11];
    const float* fc1w  = (const float*)d_in[12];
    const float* fc1b  = (const float*)d_in[13];
    const float* fc2w  = (const float*)d_in[14];
    const float* fc2b  = (const float*)d_in[15];
    float* out = (float*)d_out;

    float *hA = nullptr, *hB = nullptr;
    cudaGetSymbolAddress((void**)&hA, g_h);
    cudaGetSymbolAddress((void**)&hB, g_h2);

    bases_kernel<<<(BB * NN * KK) / 256, 256>>>(nodes, mask, modes);
    fc0_kernel<<<(BB * CC * NN) / 256, 256>>>(x, fc0w, fc0b);

    float* cur = hA;
    float* nxt = hB;
    for (int l = 0; l < LL; l++) {
        fwd_kernel<<<dim3(NSPLIT, BB), 256>>>(cur, nw);
        reduce_kernel<<<(BB * CC * KK) / 256, 256>>>();
        x0_kernel<<<dim3(CC, BB), 256>>>(cur, nw, mask);
        f0_kernel<<<BB, CC>>>(w0, l);
        mix_kernel<<<dim3(CC, BB), KK>>>(wc, ws_, l);
        inv_kernel<<<dim3(NN / 128, BB), 256>>>(cur, nxt, convw, convb, mask, l,
                                                (l != LL - 1) ? 1 : 0);
        float* t = cur; cur = nxt; nxt = t;
    }
    fc1_kernel<<<dim3(NN / 128, BB), 256>>>(cur, nxt, fc1w, fc1b);
    fc2_kernel<<<dim3(NN / 128, BB), 128>>>(nxt, out, fc2w, fc2b, mask);
}

// round 5
// speedup vs baseline: 1.3588x; 1.3588x over previous
#include <cuda_runtime.h>
#include <cuda_bf16.h>
#include <cstdint>
#include <math.h>

#define BB 8
#define NN 16384
#define KK 128
#define CC 128
#define LL 4
#define NSPLIT 32
#define XS (NN / NSPLIT)   // 512
#define PAD 40

typedef __nv_bfloat16 bf;

// ---------------- device scratch ----------------
__device__ bf g_bc_hi[BB*NN*KK], g_bc_lo[BB*NN*KK];     // bases_c [b][n][k] split
__device__ bf g_bs_hi[BB*NN*KK], g_bs_lo[BB*NN*KK];     // bases_s [b][n][k] split
__device__ bf g_wbc_hi[BB*KK*NN], g_wbc_lo[BB*KK*NN];   // (cos*mask*nw)^T [b][k][n] split
__device__ bf g_wbs_hi[BB*KK*NN], g_wbs_lo[BB*KK*NN];
__device__ float g_h[BB*CC*NN];                          // fp32 h [b][c][n]
__device__ float g_h2[BB*CC*NN];
__device__ bf g_hs_hi[BB*CC*NN], g_hs_lo[BB*CC*NN];     // split of current h
__device__ float g_pc[NSPLIT*BB*CC*KK], g_ps[NSPLIT*BB*CC*KK];
__device__ float g_xc[BB*CC*KK], g_xs[BB*CC*KK];
__device__ float g_x0v[BB*CC], g_f0v[BB*CC];
__device__ bf g_fcw_hi[BB*CC*KK], g_fcw_lo[BB*CC*KK];   // 2*f_c_hat split
__device__ bf g_fsw_hi[BB*CC*KK], g_fsw_lo[BB*CC*KK];   // -2*f_s_hat split
__device__ float g_yspec[BB*CC*NN];                      // spectral inverse output (fp32)

// ---------------- helpers ----------------
__device__ __forceinline__ void split_bf(float v, bf& h, bf& l) {
    h = __float2bfloat16(v);
    l = __float2bfloat16(v - __bfloat162float(h));
}
__device__ __forceinline__ float gelu_exact(float v) {
    return 0.5f * v * (1.0f + erff(v * 0.70710678118654752f));
}
#define MMA(d, a0, a1, a2, a3, b0, b1) \
    asm volatile("mma.sync.aligned.m16n8k16.row.col.f32.bf16.bf16.f32 " \
        "{%0,%1,%2,%3}, {%4,%5,%6,%7}, {%8,%9}, {%0,%1,%2,%3};" \
        : "+f"((d)[0]), "+f"((d)[1]), "+f"((d)[2]), "+f"((d)[3]) \
        : "r"(a0), "r"(a1), "r"(a2), "r"(a3), "r"(b0), "r"(b1))

__device__ __forceinline__ void cp_tile(bf* dst, const bf* __restrict__ src, size_t ldm, int tid) {
#pragma unroll
    for (int j = 0; j < 2; j++) {
        int idx = tid + j * 256;
        int row = idx >> 2, q = idx & 3;
        *(uint4*)(dst + row * PAD + q * 8) = *(const uint4*)(src + (size_t)row * ldm + q * 8);
    }
}

__device__ __forceinline__ void gemm_chunk(const bf* Ah, const bf* Al, const bf* Bh, const bf* Bl,
                                           float acc[4][4][4], int g, int tg, int m0, int n0) {
#pragma unroll
    for (int ks = 0; ks < 32; ks += 16) {
        uint32_t bh[4][2], bl[4][2];
#pragma unroll
        for (int nt = 0; nt < 4; nt++) {
            const bf* p = Bh + (n0 + nt * 8 + g) * PAD + ks + tg * 2;
            bh[nt][0] = *(const uint32_t*)p;
            bh[nt][1] = *(const uint32_t*)(p + 8);
            const bf* q = Bl + (n0 + nt * 8 + g) * PAD + ks + tg * 2;
            bl[nt][0] = *(const uint32_t*)q;
            bl[nt][1] = *(const uint32_t*)(q + 8);
        }
#pragma unroll
        for (int mt = 0; mt < 4; mt++) {
            const bf* p = Ah + (m0 + mt * 16 + g) * PAD + ks + tg * 2;
            uint32_t ah0 = *(const uint32_t*)p;
            uint32_t ah1 = *(const uint32_t*)(p + 8 * PAD);
            uint32_t ah2 = *(const uint32_t*)(p + 8);
            uint32_t ah3 = *(const uint32_t*)(p + 8 * PAD + 8);
            const bf* q = Al + (m0 + mt * 16 + g) * PAD + ks + tg * 2;
            uint32_t al0 = *(const uint32_t*)q;
            uint32_t al1 = *(const uint32_t*)(q + 8 * PAD);
            uint32_t al2 = *(const uint32_t*)(q + 8);
            uint32_t al3 = *(const uint32_t*)(q + 8 * PAD + 8);
#pragma unroll
            for (int nt = 0; nt < 4; nt++) {
                MMA(acc[mt][nt], ah0, ah1, ah2, ah3, bh[nt][0], bh[nt][1]);
                MMA(acc[mt][nt], ah0, ah1, ah2, ah3, bl[nt][0], bl[nt][1]);
                MMA(acc[mt][nt], al0, al1, al2, al3, bh[nt][0], bh[nt][1]);
            }
        }
    }
}

// ---------------- producers ----------------
__global__ void bases_nk_kernel(const float* __restrict__ nodes, const float* __restrict__ mask,
                                const float* __restrict__ modes) {
    int gid = blockIdx.x * blockDim.x + threadIdx.x;
    int k = gid & (KK - 1);
    int bn = gid >> 7;
    float m = mask[bn];
    float t = nodes[bn*2] * __ldg(&modes[k*2]) + nodes[bn*2+1] * __ldg(&modes[k*2+1]);
    float s, c; sincosf(t, &s, &c);
    bf h, l;
    split_bf(c * m, h, l); g_bc_hi[gid] = h; g_bc_lo[gid] = l;
    split_bf(s * m, h, l); g_bs_hi[gid] = h; g_bs_lo[gid] = l;
}
__global__ void basesT_kernel(const float* __restrict__ nodes, const float* __restrict__ mask,
                              const float* __restrict__ nw, const float* __restrict__ modes) {
    __shared__ uint32_t Tc[KK*32], Tsn[KK*32];
    int n0 = blockIdx.x * 32, b = blockIdx.y, tid = threadIdx.x;
    for (int idx = tid; idx < KK*32; idx += 256) {
        int n = idx & 31, k = idx >> 5;
        int bn = b * NN + n0 + n;
        float f = mask[bn] * nw[bn];
        float t = nodes[bn*2] * __ldg(&modes[k*2]) + nodes[bn*2+1] * __ldg(&modes[k*2+1]);
        float s, c; sincosf(t, &s, &c);
        bf h, l;
        split_bf(c * f, h, l);
        Tc[idx] = (uint32_t)__bfloat16_as_ushort(h) | ((uint32_t)__bfloat16_as_ushort(l) << 16);
        split_bf(s * f, h, l);
        Tsn[idx] = (uint32_t)__bfloat16_as_ushort(h) | ((uint32_t)__bfloat16_as_ushort(l) << 16);
    }
    __syncthreads();
    for (int idx = tid; idx < KK*32; idx += 256) {
        int n = idx & 31, k = idx >> 5;
        size_t o = ((size_t)(b * KK + k)) * NN + n0 + n;
        uint32_t vc = Tc[idx], vs = Tsn[idx];
        g_wbc_hi[o] = __ushort_as_bfloat16((unsigned short)(vc & 0xffff));
        g_wbc_lo[o] = __ushort_as_bfloat16((unsigned short)(vc >> 16));
        g_wbs_hi[o] = __ushort_as_bfloat16((unsigned short)(vs & 0xffff));
        g_wbs_lo[o] = __ushort_as_bfloat16((unsigned short)(vs >> 16));
    }
}
__global__ void fc0_kernel(const float* __restrict__ x, const float* __restrict__ w,
                           const float* __restrict__ bias) {
    int gid = blockIdx.x * blockDim.x + threadIdx.x;   // (b,c,n), n fastest
    int n = gid & (NN-1), c = (gid >> 14) & (CC-1), b = gid >> 21;
    const float* xp = x + ((size_t)b*NN + n)*3;
    g_h[gid] = bias[c] + xp[0]*w[c] + xp[1]*w[CC+c] + xp[2]*w[2*CC+c];
}
__global__ void split_h_kernel(const float* __restrict__ h) {
    int gid = blockIdx.x * blockDim.x + threadIdx.x;
    bf hi, lo; split_bf(h[gid], hi, lo);
    g_hs_hi[gid] = hi; g_hs_lo[gid] = lo;
}

// ---------------- forward projection GEMM (MMA) ----------------
__global__ __launch_bounds__(256) void gemm_fwd(const bf* __restrict__ Bhg, const bf* __restrict__ Blg,
                                                float* __restrict__ outp) {
    __shared__ bf Ah[128*PAD], Al[128*PAD], Bh[128*PAD], Bl[128*PAD];
    int split = blockIdx.x, b = blockIdx.y;
    int tid = threadIdx.x, w = tid >> 5, lane = tid & 31, g = lane >> 2, tg = lane & 3;
    int m0 = (w & 1) * 64, n0 = (w >> 1) * 32;
    const bf* As_h = g_hs_hi + (size_t)b * CC * NN;
    const bf* As_l = g_hs_lo + (size_t)b * CC * NN;
    const bf* Bs_h = Bhg + (size_t)b * KK * NN;
    const bf* Bs_l = Blg + (size_t)b * KK * NN;
    float acc[4][4][4];
#pragma unroll
    for (int i = 0; i < 4; i++)
#pragma unroll
        for (int j = 0; j < 4; j++)
#pragma unroll
            for (int q = 0; q < 4; q++) acc[i][j][q] = 0.f;

    for (int ch = 0; ch < XS / 32; ch++) {
        int x0 = split * XS + ch * 32;
        cp_tile(Ah, As_h + x0, NN, tid);
        cp_tile(Al, As_l + x0, NN, tid);
        cp_tile(Bh, Bs_h + x0, NN, tid);
        cp_tile(Bl, Bs_l + x0, NN, tid);
        __syncthreads();
        gemm_chunk(Ah, Al, Bh, Bl, acc, g, tg, m0, n0);
        __syncthreads();
    }
    float* pp = outp + (size_t)(split * BB + b) * CC * KK;
#pragma unroll
    for (int mt = 0; mt < 4; mt++) {
        int r0 = m0 + mt * 16 + g;
#pragma unroll
        for (int nt = 0; nt < 4; nt++) {
            int n = n0 + nt * 8 + tg * 2;
            *(float2*)&pp[r0 * KK + n] = make_float2(acc[mt][nt][0], acc[mt][nt][1]);
            *(float2*)&pp[(r0 + 8) * KK + n] = make_float2(acc[mt][nt][2], acc[mt][nt][3]);
        }
    }
}

// ---------------- inverse spectral projection (MMA): y = 2fc@bc^T - 2fs@bs^T ----------------
__global__ __launch_bounds__(256) void inv_spec(float* __restrict__ y) {
    __shared__ bf Ah[128*PAD], Al[128*PAD], Bh[128*PAD], Bl[128*PAD];
    int xb = blockIdx.x * 128, b = blockIdx.y;
    int tid = threadIdx.x, w = tid >> 5, lane = tid & 31, g = lane >> 2, tg = lane & 3;
    int m0 = (w & 1) * 64, n0 = (w >> 1) * 32;
    float acc[4][4][4];
#pragma unroll
    for (int i = 0; i < 4; i++)
#pragma unroll
        for (int j = 0; j < 4; j++)
#pragma unroll
            for (int q = 0; q < 4; q++) acc[i][j][q] = 0.f;

    for (int pass = 0; pass < 2; pass++) {
        const bf* pAh = (pass ? g_fsw_hi : g_fcw_hi) + (size_t)b*CC*KK;
        const bf* pAl = (pass ? g_fsw_lo : g_fcw_lo) + (size_t)b*CC*KK;
        const bf* pBh = (pass ? g_bs_hi : g_bc_hi) + ((size_t)b*NN + xb)*KK;
        const bf* pBl = (pass ? g_bs_lo : g_bc_lo) + ((size_t)b*NN + xb)*KK;
        for (int ch = 0; ch < 4; ch++) {
            int k0 = ch * 32;
            cp_tile(Ah, pAh + k0, 128, tid);
            cp_tile(Al, pAl + k0, 128, tid);
            cp_tile(Bh, pBh + k0, 128, tid);
            cp_tile(Bl, pBl + k0, 128, tid);
            __syncthreads();
            gemm_chunk(Ah, Al, Bh, Bl, acc, g, tg, m0, n0);
            __syncthreads();
        }
    }
#pragma unroll
    for (int mt = 0; mt < 4; mt++) {
        int r0 = m0 + mt * 16 + g;
        float* p0 = y + ((size_t)b * CC + r0) * NN + xb;
        float* p1 = y + ((size_t)b * CC + r0 + 8) * NN + xb;
#pragma unroll
        for (int nt = 0; nt < 4; nt++) {
            int n = n0 + nt * 8 + tg * 2;
            *(float2*)(p0 + n) = make_float2(acc[mt][nt][0], acc[mt][nt][1]);
            *(float2*)(p1 + n) = make_float2(acc[mt][nt][2], acc[mt][nt][3]);
        }
    }
}

// ---------------- small kernels ----------------
__global__ void reduce_kernel() {
    int gid = blockIdx.x * blockDim.x + threadIdx.x;
    float sc = 0.f, ss = 0.f;
#pragma unroll
    for (int s = 0; s < NSPLIT; s++) {
        sc += g_pc[(size_t)s * BB * CC * KK + gid];
        ss += g_ps[(size_t)s * BB * CC * KK + gid];
    }
    g_xc[gid] = sc;
    g_xs[gid] = -ss;
}
__global__ void x0_kernel(const float* __restrict__ h, const float* __restrict__ nw,
                          const float* __restrict__ mask) {
    int i = blockIdx.x, b = blockIdx.y;
    const float* hr = h + ((size_t)b * CC + i) * NN;
    const float* nwb = nw + b * NN;
    const float* mb = mask + b * NN;
    float acc = 0.f;
    for (int x = threadIdx.x; x < NN; x += 256)
        acc += hr[x] * nwb[x] * mb[x];
    __shared__ float red[256];
    red[threadIdx.x] = acc;
    __syncthreads();
    for (int s = 128; s > 0; s >>= 1) {
        if (threadIdx.x < s) red[threadIdx.x] += red[threadIdx.x + s];
        __syncthreads();
    }
    if (threadIdx.x == 0) g_x0v[b * CC + i] = red[0];
}
__global__ void f0_kernel(const float* __restrict__ w0, int l) {
    int b = blockIdx.x, o = threadIdx.x;
    __shared__ float xs[CC];
    xs[o] = g_x0v[b * CC + o];
    __syncthreads();
    const float* w = w0 + (size_t)l * CC * CC;
    float acc = 0.f;
#pragma unroll 8
    for (int i = 0; i < CC; i++) acc += xs[i] * w[i * CC + o];
    g_f0v[b * CC + o] = acc;
}
__global__ void mix_kernel(const float* __restrict__ wc, const float* __restrict__ ws, int l) {
    int o = blockIdx.x, b = blockIdx.y, k = threadIdx.x;
    const float* wcl = wc + (size_t)l * CC * CC * KK;
    const float* wsl = ws + (size_t)l * CC * CC * KK;
    float fcA = 0.f, fsA = 0.f;
#pragma unroll 4
    for (int i = 0; i < CC; i++) {
        float xc = g_xc[(b * CC + i) * KK + k];
        float xv = g_xs[(b * CC + i) * KK + k];
        float wcv = wcl[((size_t)i * CC + o) * KK + k];
        float wsv = wsl[((size_t)i * CC + o) * KK + k];
        fcA += xc * wcv - xv * wsv;
        fsA += xv * wcv + xc * wsv;
    }
    int idx = (b * CC + o) * KK + k;
    bf h, l2;
    split_bf(2.0f * fcA, h, l2);  g_fcw_hi[idx] = h; g_fcw_lo[idx] = l2;
    split_bf(-2.0f * fsA, h, l2); g_fsw_hi[idx] = h; g_fsw_lo[idx] = l2;
}

// ---------------- conv (fp32 FFMA) + yspec + bias + f0*mask + gelu ----------------
__global__ __launch_bounds__(256, 2) void conv_kernel(const float* __restrict__ hin,
                                                      float* __restrict__ hout,
                                                      const float* __restrict__ convw,
                                                      const float* __restrict__ convb,
                                                      const float* __restrict__ mask,
                                                      const float* __restrict__ yspec,
                                                      int l, int apply_gelu) {
    __shared__ float Ast[32][128];
    __shared__ float Bs[32][128];
    int x0 = blockIdx.x * 128, b = blockIdx.y;
    int tid = threadIdx.x;
    int tx = tid & 15, ty = tid >> 4;
    int o0 = ty * 8, xf0 = tx * 8;
    float acc[8][8];
#pragma unroll
    for (int m = 0; m < 8; m++)
#pragma unroll
        for (int n = 0; n < 8; n++) acc[m][n] = 0.f;

    const float* A = convw + (size_t)l * CC * CC;
    const float* Bsrc = hin + (size_t)b * CC * NN;
    for (int c0 = 0; c0 < 128; c0 += 32) {
#pragma unroll
        for (int j = 0; j < 4; j++) {
            int idx = tid + j * 256;
            int row = idx >> 3, c4 = (idx & 7) << 2;
            float4 v = *(const float4*)(A + row * 128 + c0 + c4);
            Ast[c4 + 0][row] = v.x; Ast[c4 + 1][row] = v.y;
            Ast[c4 + 2][row] = v.z; Ast[c4 + 3][row] = v.w;
        }
#pragma unroll
        for (int j = 0; j < 4; j++) {
            int idx = tid + j * 256;
            int row = idx >> 5, c4 = (idx & 31) << 2;
            *(float4*)&Bs[row][c4] = *(const float4*)(Bsrc + (size_t)(c0 + row) * NN + x0 + c4);
        }
        __syncthreads();
#pragma unroll 4
        for (int cc = 0; cc < 32; cc++) {
            float4 a0 = *(float4*)&Ast[cc][o0];
            float4 a1 = *(float4*)&Ast[cc][o0 + 4];
            float4 b0 = *(float4*)&Bs[cc][xf0];
            float4 b1 = *(float4*)&Bs[cc][xf0 + 4];
            float av[8] = {a0.x, a0.y, a0.z, a0.w, a1.x, a1.y, a1.z, a1.w};
            float bv[8] = {b0.x, b0.y, b0.z, b0.w, b1.x, b1.y, b1.z, b1.w};
#pragma unroll
            for (int m = 0; m < 8; m++)
#pragma unroll
                for (int n = 0; n < 8; n++) acc[m][n] += av[m] * bv[n];
        }
        __syncthreads();
    }
    const float* mb = mask + (size_t)b * NN + x0 + xf0;
#pragma unroll
    for (int m = 0; m < 8; m++) {
        int o = o0 + m;
        float f0v = g_f0v[b * CC + o];
        float cb = convb[l * CC + o];
        const float* yp = yspec + ((size_t)b * CC + o) * NN + x0 + xf0;
        float* outp = hout + ((size_t)b * CC + o) * NN + x0 + xf0;
#pragma unroll
        for (int n = 0; n < 8; n++) {
            float v = acc[m][n] + yp[n] + f0v * mb[n] + cb;
            if (apply_gelu) v = gelu_exact(v);
            outp[n] = v;
        }
    }
}

// ---------------- fc1 (fp32 FFMA) + fc2 ----------------
__global__ __launch_bounds__(256, 2) void fc1_kernel(const float* __restrict__ hin,
                                                     float* __restrict__ hout,
                                                     const float* __restrict__ w1,
                                                     const float* __restrict__ b1) {
    __shared__ float Ast[32][128];
    __shared__ float Bs[32][128];
    int x0 = blockIdx.x * 128, b = blockIdx.y;
    int tid = threadIdx.x;
    int tx = tid & 15, ty = tid >> 4;
    int o0 = ty * 8, xf0 = tx * 8;
    float acc[8][8];
#pragma unroll
    for (int m = 0; m < 8; m++)
#pragma unroll
        for (int n = 0; n < 8; n++) acc[m][n] = 0.f;

    for (int c0 = 0; c0 < 128; c0 += 32) {
#pragma unroll
        for (int j = 0; j < 4; j++) {
            int idx = tid + j * 256;
            int row = idx >> 5, c4 = (idx & 31) << 2;
            *(float4*)&Ast[row][c4] = *(const float4*)(w1 + (c0 + row) * 128 + c4);
        }
#pragma unroll
        for (int j = 0; j < 4; j++) {
            int idx = tid + j * 256;
            int row = idx >> 5, c4 = (idx & 31) << 2;
            *(float4*)&Bs[row][c4] = *(const float4*)(hin + ((size_t)b * CC + c0 + row) * NN + x0 + c4);
        }
        __syncthreads();
#pragma unroll 4
        for (int cc = 0; cc < 32; cc++) {
            float4 a0 = *(float4*)&Ast[cc][o0];
            float4 a1 = *(float4*)&Ast[cc][o0 + 4];
            float4 b0 = *(float4*)&Bs[cc][xf0];
            float4 b1v = *(float4*)&Bs[cc][xf0 + 4];
            float av[8] = {a0.x, a0.y, a0.z, a0.w, a1.x, a1.y, a1.z, a1.w};
            float bv[8] = {b0.x, b0.y, b0.z, b0.w, b1v.x, b1v.y, b1v.z, b1v.w};
#pragma unroll
            for (int m = 0; m < 8; m++)
#pragma unroll
                for (int n = 0; n < 8; n++) acc[m][n] += av[m] * bv[n];
        }
        __syncthreads();
    }
#pragma unroll
    for (int m = 0; m < 8; m++) {
        int jj = o0 + m;
        float bj = b1[jj];
        float* outp = hout + ((size_t)b * CC + jj) * NN + x0 + xf0;
#pragma unroll
        for (int n = 0; n < 8; n++) outp[n] = gelu_exact(acc[m][n] + bj);
    }
}
__global__ void fc2_kernel(const float* __restrict__ hin, float* __restrict__ out,
                           const float* __restrict__ w2, const float* __restrict__ b2,
                           const float* __restrict__ mask) {
    __shared__ float ws[128];
    int x0 = blockIdx.x * 128, b = blockIdx.y;
    ws[threadIdx.x] = w2[threadIdx.x];
    __syncthreads();
    int x = x0 + threadIdx.x;
    float acc = 0.f;
#pragma unroll 8
    for (int j = 0; j < 128; j++) acc += hin[((size_t)b * CC + j) * NN + x] * ws[j];
    out[b * NN + x] = (acc + b2[0]) * mask[b * NN + x];
}

// ---------------- launch ----------------
extern "C" void kernel_launch(void* const* d_in, const int* in_sizes, int n_in,
                              void* d_out, int out_size) {
    const float* x     = (const float*)d_in[0];
    const float* nodes = (const float*)d_in[1];
    const float* mask  = (const float*)d_in[2];
    const float* nw    = (const float*)d_in[3];
    const float* modes = (const float*)d_in[4];
    const float* fc0w  = (const float*)d_in[5];
    const float* fc0b  = (const float*)d_in[6];
    const float* wc    = (const float*)d_in[7];
    const float* ws_   = (const float*)d_in[8];
    const float* w0    = (const float*)d_in[9];
    const float* convw = (const float*)d_in[10];
    const float* convb = (const float*)d_in[11];
    const float* fc1w  = (const float*)d_in[12];
    const float* fc1b  = (const float*)d_in[13];
    const float* fc2w  = (const float*)d_in[14];
    const float* fc2b  = (const float*)d_in[15];
    float* out = (float*)d_out;

    float *hA, *hB, *pcp, *psp, *ysp;
    bf *wbch, *wbcl, *wbsh, *wbsl;
    cudaGetSymbolAddress((void**)&hA, g_h);
    cudaGetSymbolAddress((void**)&hB, g_h2);
    cudaGetSymbolAddress((void**)&pcp, g_pc);
    cudaGetSymbolAddress((void**)&psp, g_ps);
    cudaGetSymbolAddress((void**)&ysp, g_yspec);
    cudaGetSymbolAddress((void**)&wbch, g_wbc_hi);
    cudaGetSymbolAddress((void**)&wbcl, g_wbc_lo);
    cudaGetSymbolAddress((void**)&wbsh, g_wbs_hi);
    cudaGetSymbolAddress((void**)&wbsl, g_wbs_lo);

    bases_nk_kernel<<<(BB*NN*KK)/256, 256>>>(nodes, mask, modes);
    basesT_kernel<<<dim3(NN/32, BB), 256>>>(nodes, mask, nw, modes);
    fc0_kernel<<<(BB*CC*NN)/256, 256>>>(x, fc0w, fc0b);

    float* cur = hA;
    float* nxt = hB;
    for (int l = 0; l < LL; l++) {
        split_h_kernel<<<(BB*CC*NN)/256, 256>>>(cur);
        gemm_fwd<<<dim3(NSPLIT, BB), 256>>>(wbch, wbcl, pcp);
        gemm_fwd<<<dim3(NSPLIT, BB), 256>>>(wbsh, wbsl, psp);
        reduce_kernel<<<(BB*CC*KK)/256, 256>>>();
        x0_kernel<<<dim3(CC, BB), 256>>>(cur, nw, mask);
        f0_kernel<<<BB, CC>>>(w0, l);
        mix_kernel<<<dim3(CC, BB), KK>>>(wc, ws_, l);
        inv_spec<<<dim3(NN/128, BB), 256>>>(ysp);
        conv_kernel<<<dim3(NN/128, BB), 256>>>(cur, nxt, convw, convb, mask, ysp, l,
                                               (l != LL-1) ? 1 : 0);
        float* t = cur; cur = nxt; nxt = t;
    }
    fc1_kernel<<<dim3(NN/128, BB), 256>>>(cur, nxt, fc1w, fc1b);
    fc2_kernel<<<dim3(NN/128, BB), 128>>>(nxt, out, fc2w, fc2b, mask);
}

// round 7
// speedup vs baseline: 1.5851x; 1.1666x over previous
#include <cuda_runtime.h>
#include <cuda_bf16.h>
#include <cstdint>
#include <math.h>

#define BB 8
#define NN 16384
#define KK 128
#define CC 128
#define LL 4
#define NSPLIT 32
#define XS (NN / NSPLIT)   // 512
#define PAD 40

typedef __nv_bfloat16 bf;

// ---------------- device scratch ----------------
__device__ bf g_bc_hi[BB*NN*KK], g_bc_lo[BB*NN*KK];     // bases_c [b][n][k] split
__device__ bf g_bs_hi[BB*NN*KK], g_bs_lo[BB*NN*KK];     // bases_s [b][n][k] split
__device__ bf g_wbc_hi[BB*KK*NN], g_wbc_lo[BB*KK*NN];   // (cos*mask*nw)^T [b][k][n] split
__device__ bf g_wbs_hi[BB*KK*NN], g_wbs_lo[BB*KK*NN];
__device__ float g_h[BB*CC*NN];                          // fp32 h [b][c][n]
__device__ float g_h2[BB*CC*NN];
__device__ bf g_hs_hi[BB*CC*NN], g_hs_lo[BB*CC*NN];     // split of current h [b][c][n]
__device__ bf g_nch[BB*NN*CC], g_ncl[BB*NN*CC];         // split of current h [b][n][c]
__device__ float g_pc[NSPLIT*BB*CC*KK], g_ps[NSPLIT*BB*CC*KK];
__device__ float g_xc[BB*CC*KK], g_xs[BB*CC*KK];
__device__ float g_x0v[BB*CC], g_f0v[BB*CC];
__device__ bf g_fcw_hi[BB*CC*KK], g_fcw_lo[BB*CC*KK];   // 2*f_c_hat split
__device__ bf g_fsw_hi[BB*CC*KK], g_fsw_lo[BB*CC*KK];   // -2*f_s_hat split
__device__ bf g_cw_hi[LL*CC*CC], g_cw_lo[LL*CC*CC];     // conv_w split [l][o][i]

// ---------------- helpers ----------------
__device__ __forceinline__ void split_bf(float v, bf& h, bf& l) {
    h = __float2bfloat16(v);
    l = __float2bfloat16(v - __bfloat162float(h));
}
__device__ __forceinline__ float gelu_exact(float v) {
    return 0.5f * v * (1.0f + erff(v * 0.70710678118654752f));
}
#define MMA(d, a0, a1, a2, a3, b0, b1) \
    asm volatile("mma.sync.aligned.m16n8k16.row.col.f32.bf16.bf16.f32 " \
        "{%0,%1,%2,%3}, {%4,%5,%6,%7}, {%8,%9}, {%0,%1,%2,%3};" \
        : "+f"((d)[0]), "+f"((d)[1]), "+f"((d)[2]), "+f"((d)[3]) \
        : "r"(a0), "r"(a1), "r"(a2), "r"(a3), "r"(b0), "r"(b1))

__device__ __forceinline__ void cp_tile(bf* dst, const bf* __restrict__ src, size_t ldm, int tid) {
#pragma unroll
    for (int j = 0; j < 2; j++) {
        int idx = tid + j * 256;
        int row = idx >> 2, q = idx & 3;
        *(uint4*)(dst + row * PAD + q * 8) = *(const uint4*)(src + (size_t)row * ldm + q * 8);
    }
}

__device__ __forceinline__ void gemm_chunk(const bf* Ah, const bf* Al, const bf* Bh, const bf* Bl,
                                           float acc[4][4][4], int g, int tg, int m0, int n0) {
#pragma unroll
    for (int ks = 0; ks < 32; ks += 16) {
        uint32_t bh[4][2], bl[4][2];
#pragma unroll
        for (int nt = 0; nt < 4; nt++) {
            const bf* p = Bh + (n0 + nt * 8 + g) * PAD + ks + tg * 2;
            bh[nt][0] = *(const uint32_t*)p;
            bh[nt][1] = *(const uint32_t*)(p + 8);
            const bf* q = Bl + (n0 + nt * 8 + g) * PAD + ks + tg * 2;
            bl[nt][0] = *(const uint32_t*)q;
            bl[nt][1] = *(const uint32_t*)(q + 8);
        }
#pragma unroll
        for (int mt = 0; mt < 4; mt++) {
            const bf* p = Ah + (m0 + mt * 16 + g) * PAD + ks + tg * 2;
            uint32_t ah0 = *(const uint32_t*)p;
            uint32_t ah1 = *(const uint32_t*)(p + 8 * PAD);
            uint32_t ah2 = *(const uint32_t*)(p + 8);
            uint32_t ah3 = *(const uint32_t*)(p + 8 * PAD + 8);
            const bf* q = Al + (m0 + mt * 16 + g) * PAD + ks + tg * 2;
            uint32_t al0 = *(const uint32_t*)q;
            uint32_t al1 = *(const uint32_t*)(q + 8 * PAD);
            uint32_t al2 = *(const uint32_t*)(q + 8);
            uint32_t al3 = *(const uint32_t*)(q + 8 * PAD + 8);
#pragma unroll
            for (int nt = 0; nt < 4; nt++) {
                MMA(acc[mt][nt], ah0, ah1, ah2, ah3, bh[nt][0], bh[nt][1]);
                MMA(acc[mt][nt], ah0, ah1, ah2, ah3, bl[nt][0], bl[nt][1]);
                MMA(acc[mt][nt], al0, al1, al2, al3, bh[nt][0], bh[nt][1]);
            }
        }
    }
}

// ---------------- producers ----------------
__global__ void bases_nk_kernel(const float* __restrict__ nodes, const float* __restrict__ mask,
                                const float* __restrict__ modes) {
    int gid = blockIdx.x * blockDim.x + threadIdx.x;
    int k = gid & (KK - 1);
    int bn = gid >> 7;
    float m = mask[bn];
    float t = nodes[bn*2] * __ldg(&modes[k*2]) + nodes[bn*2+1] * __ldg(&modes[k*2+1]);
    float s, c; sincosf(t, &s, &c);
    bf h, l;
    split_bf(c * m, h, l); g_bc_hi[gid] = h; g_bc_lo[gid] = l;
    split_bf(s * m, h, l); g_bs_hi[gid] = h; g_bs_lo[gid] = l;
}
__global__ void basesT_kernel(const float* __restrict__ nodes, const float* __restrict__ mask,
                              const float* __restrict__ nw, const float* __restrict__ modes) {
    __shared__ uint32_t Tc[KK*32], Tsn[KK*32];
    int n0 = blockIdx.x * 32, b = blockIdx.y, tid = threadIdx.x;
    for (int idx = tid; idx < KK*32; idx += 256) {
        int n = idx & 31, k = idx >> 5;
        int bn = b * NN + n0 + n;
        float f = mask[bn] * nw[bn];
        float t = nodes[bn*2] * __ldg(&modes[k*2]) + nodes[bn*2+1] * __ldg(&modes[k*2+1]);
        float s, c; sincosf(t, &s, &c);
        bf h, l;
        split_bf(c * f, h, l);
        Tc[idx] = (uint32_t)__bfloat16_as_ushort(h) | ((uint32_t)__bfloat16_as_ushort(l) << 16);
        split_bf(s * f, h, l);
        Tsn[idx] = (uint32_t)__bfloat16_as_ushort(h) | ((uint32_t)__bfloat16_as_ushort(l) << 16);
    }
    __syncthreads();
    for (int idx = tid; idx < KK*32; idx += 256) {
        int n = idx & 31, k = idx >> 5;
        size_t o = ((size_t)(b * KK + k)) * NN + n0 + n;
        uint32_t vc = Tc[idx], vs = Tsn[idx];
        g_wbc_hi[o] = __ushort_as_bfloat16((unsigned short)(vc & 0xffff));
        g_wbc_lo[o] = __ushort_as_bfloat16((unsigned short)(vc >> 16));
        g_wbs_hi[o] = __ushort_as_bfloat16((unsigned short)(vs & 0xffff));
        g_wbs_lo[o] = __ushort_as_bfloat16((unsigned short)(vs >> 16));
    }
}
__global__ void fc0_kernel(const float* __restrict__ x, const float* __restrict__ w,
                           const float* __restrict__ bias) {
    int gid = blockIdx.x * blockDim.x + threadIdx.x;   // (b,c,n), n fastest
    int n = gid & (NN-1), c = (gid >> 14) & (CC-1), b = gid >> 21;
    const float* xp = x + ((size_t)b*NN + n)*3;
    g_h[gid] = bias[c] + xp[0]*w[c] + xp[1]*w[CC+c] + xp[2]*w[2*CC+c];
}
__global__ void split_h_kernel(const float* __restrict__ h) {
    int gid = blockIdx.x * blockDim.x + threadIdx.x;
    bf hi, lo; split_bf(h[gid], hi, lo);
    g_hs_hi[gid] = hi; g_hs_lo[gid] = lo;
}
__global__ void split_convw(const float* __restrict__ convw) {
    int gid = blockIdx.x * blockDim.x + threadIdx.x;   // LL*CC*CC
    bf h, l;
    split_bf(convw[gid], h, l);
    g_cw_hi[gid] = h; g_cw_lo[gid] = l;
}
// transpose: fp32 h [b][c][n] -> split hnc [b][n][c]
__global__ void trans_split(const float* __restrict__ h) {
    __shared__ float T[32][33];
    int n0 = blockIdx.x * 32;
    int cb = blockIdx.y & 3;
    int b = blockIdx.y >> 2;
    int c0 = cb * 32;
    int tx = threadIdx.x & 31, ty = threadIdx.x >> 5;   // 32 x 8
#pragma unroll
    for (int i = 0; i < 4; i++) {
        int c = c0 + ty + i * 8;
        T[ty + i * 8][tx] = h[((size_t)b * CC + c) * NN + n0 + tx];
    }
    __syncthreads();
#pragma unroll
    for (int i = 0; i < 4; i++) {
        int n = n0 + ty + i * 8;
        float v = T[tx][ty + i * 8];
        bf hi, lo; split_bf(v, hi, lo);
        size_t o = ((size_t)b * NN + n) * CC + c0 + tx;
        g_nch[o] = hi; g_ncl[o] = lo;
    }
}

// ---------------- forward projection GEMM (MMA) ----------------
__global__ __launch_bounds__(256) void gemm_fwd(const bf* __restrict__ Bhg, const bf* __restrict__ Blg,
                                                float* __restrict__ outp) {
    __shared__ bf Ah[128*PAD], Al[128*PAD], Bh[128*PAD], Bl[128*PAD];
    int split = blockIdx.x, b = blockIdx.y;
    int tid = threadIdx.x, w = tid >> 5, lane = tid & 31, g = lane >> 2, tg = lane & 3;
    int m0 = (w & 1) * 64, n0 = (w >> 1) * 32;
    const bf* As_h = g_hs_hi + (size_t)b * CC * NN;
    const bf* As_l = g_hs_lo + (size_t)b * CC * NN;
    const bf* Bs_h = Bhg + (size_t)b * KK * NN;
    const bf* Bs_l = Blg + (size_t)b * KK * NN;
    float acc[4][4][4];
#pragma unroll
    for (int i = 0; i < 4; i++)
#pragma unroll
        for (int j = 0; j < 4; j++)
#pragma unroll
            for (int q = 0; q < 4; q++) acc[i][j][q] = 0.f;

    for (int ch = 0; ch < XS / 32; ch++) {
        int x0 = split * XS + ch * 32;
        cp_tile(Ah, As_h + x0, NN, tid);
        cp_tile(Al, As_l + x0, NN, tid);
        cp_tile(Bh, Bs_h + x0, NN, tid);
        cp_tile(Bl, Bs_l + x0, NN, tid);
        __syncthreads();
        gemm_chunk(Ah, Al, Bh, Bl, acc, g, tg, m0, n0);
        __syncthreads();
    }
    float* pp = outp + (size_t)(split * BB + b) * CC * KK;
#pragma unroll
    for (int mt = 0; mt < 4; mt++) {
        int r0 = m0 + mt * 16 + g;
#pragma unroll
        for (int nt = 0; nt < 4; nt++) {
            int n = n0 + nt * 8 + tg * 2;
            *(float2*)&pp[r0 * KK + n] = make_float2(acc[mt][nt][0], acc[mt][nt][1]);
            *(float2*)&pp[(r0 + 8) * KK + n] = make_float2(acc[mt][nt][2], acc[mt][nt][3]);
        }
    }
}

// ---------------- fused inverse: y = 2fc@bc^T - 2fs@bs^T + conv_w@h; epilogue fp32 ----------------
__global__ __launch_bounds__(256) void inv3(const bf* __restrict__ hnc_hi, const bf* __restrict__ hnc_lo,
                                            float* __restrict__ hout,
                                            const float* __restrict__ convb,
                                            const float* __restrict__ mask,
                                            int l, int apply_gelu) {
    __shared__ bf Ah[128*PAD], Al[128*PAD], Bh[128*PAD], Bl[128*PAD];
    int xb = blockIdx.x * 128, b = blockIdx.y;
    int tid = threadIdx.x, w = tid >> 5, lane = tid & 31, g = lane >> 2, tg = lane & 3;
    int m0 = (w & 1) * 64, n0 = (w >> 1) * 32;
    float acc[4][4][4];
#pragma unroll
    for (int i = 0; i < 4; i++)
#pragma unroll
        for (int j = 0; j < 4; j++)
#pragma unroll
            for (int q = 0; q < 4; q++) acc[i][j][q] = 0.f;

    for (int pass = 0; pass < 3; pass++) {
        const bf *pAh, *pAl, *pBh, *pBl;
        if (pass == 0) {
            pAh = g_fcw_hi + (size_t)b*CC*KK; pAl = g_fcw_lo + (size_t)b*CC*KK;
            pBh = g_bc_hi + ((size_t)b*NN + xb)*KK; pBl = g_bc_lo + ((size_t)b*NN + xb)*KK;
        } else if (pass == 1) {
            pAh = g_fsw_hi + (size_t)b*CC*KK; pAl = g_fsw_lo + (size_t)b*CC*KK;
            pBh = g_bs_hi + ((size_t)b*NN + xb)*KK; pBl = g_bs_lo + ((size_t)b*NN + xb)*KK;
        } else {
            pAh = g_cw_hi + (size_t)l*CC*CC; pAl = g_cw_lo + (size_t)l*CC*CC;
            pBh = hnc_hi + ((size_t)b*NN + xb)*CC; pBl = hnc_lo + ((size_t)b*NN + xb)*CC;
        }
        for (int ch = 0; ch < 4; ch++) {
            int k0 = ch * 32;
            cp_tile(Ah, pAh + k0, 128, tid);
            cp_tile(Al, pAl + k0, 128, tid);
            cp_tile(Bh, pBh + k0, 128, tid);
            cp_tile(Bl, pBl + k0, 128, tid);
            __syncthreads();
            gemm_chunk(Ah, Al, Bh, Bl, acc, g, tg, m0, n0);
            __syncthreads();
        }
    }
#pragma unroll
    for (int mt = 0; mt < 4; mt++) {
        int r0 = m0 + mt * 16 + g, r1 = r0 + 8;
        float cb0 = convb[l * CC + r0], f00 = g_f0v[b * CC + r0];
        float cb1 = convb[l * CC + r1], f01 = g_f0v[b * CC + r1];
#pragma unroll
        for (int nt = 0; nt < 4; nt++) {
            int n = n0 + nt * 8 + tg * 2;
            float mk0 = mask[(size_t)b * NN + xb + n];
            float mk1 = mask[(size_t)b * NN + xb + n + 1];
            float v00 = acc[mt][nt][0] + cb0 + f00 * mk0;
            float v01 = acc[mt][nt][1] + cb0 + f00 * mk1;
            float v10 = acc[mt][nt][2] + cb1 + f01 * mk0;
            float v11 = acc[mt][nt][3] + cb1 + f01 * mk1;
            if (apply_gelu) {
                v00 = gelu_exact(v00); v01 = gelu_exact(v01);
                v10 = gelu_exact(v10); v11 = gelu_exact(v11);
            }
            size_t o0 = ((size_t)b * CC + r0) * NN + xb + n;
            size_t o1 = ((size_t)b * CC + r1) * NN + xb + n;
            *(float2*)(hout + o0) = make_float2(v00, v01);
            *(float2*)(hout + o1) = make_float2(v10, v11);
        }
    }
}

// ---------------- small kernels ----------------
__global__ void reduce_kernel() {
    int gid = blockIdx.x * blockDim.x + threadIdx.x;
    float sc = 0.f, ss = 0.f;
#pragma unroll
    for (int s = 0; s < NSPLIT; s++) {
        sc += g_pc[(size_t)s * BB * CC * KK + gid];
        ss += g_ps[(size_t)s * BB * CC * KK + gid];
    }
    g_xc[gid] = sc;
    g_xs[gid] = -ss;
}
__global__ void x0_kernel(const float* __restrict__ h, const float* __restrict__ nw,
                          const float* __restrict__ mask) {
    int i = blockIdx.x, b = blockIdx.y;
    const float* hr = h + ((size_t)b * CC + i) * NN;
    const float* nwb = nw + b * NN;
    const float* mb = mask + b * NN;
    float acc = 0.f;
    for (int x = threadIdx.x; x < NN; x += 256)
        acc += hr[x] * nwb[x] * mb[x];
    __shared__ float red[256];
    red[threadIdx.x] = acc;
    __syncthreads();
    for (int s = 128; s > 0; s >>= 1) {
        if (threadIdx.x < s) red[threadIdx.x] += red[threadIdx.x + s];
        __syncthreads();
    }
    if (threadIdx.x == 0) g_x0v[b * CC + i] = red[0];
}
__global__ void f0_kernel(const float* __restrict__ w0, int l) {
    int b = blockIdx.x, o = threadIdx.x;
    __shared__ float xs[CC];
    xs[o] = g_x0v[b * CC + o];
    __syncthreads();
    const float* w = w0 + (size_t)l * CC * CC;
    float acc = 0.f;
#pragma unroll 8
    for (int i = 0; i < CC; i++) acc += xs[i] * w[i * CC + o];
    g_f0v[b * CC + o] = acc;
}
__global__ void mix_kernel(const float* __restrict__ wc, const float* __restrict__ ws, int l) {
    int o = blockIdx.x, b = blockIdx.y, k = threadIdx.x;
    const float* wcl = wc + (size_t)l * CC * CC * KK;
    const float* wsl = ws + (size_t)l * CC * CC * KK;
    float fcA = 0.f, fsA = 0.f;
#pragma unroll 4
    for (int i = 0; i < CC; i++) {
        float xc = g_xc[(b * CC + i) * KK + k];
        float xv = g_xs[(b * CC + i) * KK + k];
        float wcv = wcl[((size_t)i * CC + o) * KK + k];
        float wsv = wsl[((size_t)i * CC + o) * KK + k];
        fcA += xc * wcv - xv * wsv;
        fsA += xv * wcv + xc * wsv;
    }
    int idx = (b * CC + o) * KK + k;
    bf h, l2;
    split_bf(2.0f * fcA, h, l2);  g_fcw_hi[idx] = h; g_fcw_lo[idx] = l2;
    split_bf(-2.0f * fsA, h, l2); g_fsw_hi[idx] = h; g_fsw_lo[idx] = l2;
}

// ---------------- fc1 (fp32 FFMA, validated) + fc2 ----------------
__global__ __launch_bounds__(256, 2) void fc1_kernel(const float* __restrict__ hin,
                                                     float* __restrict__ hout,
                                                     const float* __restrict__ w1,
                                                     const float* __restrict__ b1) {
    __shared__ float Ast[32][128];
    __shared__ float Bs[32][128];
    int x0 = blockIdx.x * 128, b = blockIdx.y;
    int tid = threadIdx.x;
    int tx = tid & 15, ty = tid >> 4;
    int o0 = ty * 8, xf0 = tx * 8;
    float acc[8][8];
#pragma unroll
    for (int m = 0; m < 8; m++)
#pragma unroll
        for (int n = 0; n < 8; n++) acc[m][n] = 0.f;

    for (int c0 = 0; c0 < 128; c0 += 32) {
#pragma unroll
        for (int j = 0; j < 4; j++) {
            int idx = tid + j * 256;
            int row = idx >> 5, c4 = (idx & 31) << 2;
            *(float4*)&Ast[row][c4] = *(const float4*)(w1 + (c0 + row) * 128 + c4);
        }
#pragma unroll
        for (int j = 0; j < 4; j++) {
            int idx = tid + j * 256;
            int row = idx >> 5, c4 = (idx & 31) << 2;
            *(float4*)&Bs[row][c4] = *(const float4*)(hin + ((size_t)b * CC + c0 + row) * NN + x0 + c4);
        }
        __syncthreads();
#pragma unroll 4
        for (int cc = 0; cc < 32; cc++) {
            float4 a0 = *(float4*)&Ast[cc][o0];
            float4 a1 = *(float4*)&Ast[cc][o0 + 4];
            float4 b0 = *(float4*)&Bs[cc][xf0];
            float4 b1v = *(float4*)&Bs[cc][xf0 + 4];
            float av[8] = {a0.x, a0.y, a0.z, a0.w, a1.x, a1.y, a1.z, a1.w};
            float bv[8] = {b0.x, b0.y, b0.z, b0.w, b1v.x, b1v.y, b1v.z, b1v.w};
#pragma unroll
            for (int m = 0; m < 8; m++)
#pragma unroll
                for (int n = 0; n < 8; n++) acc[m][n] += av[m] * bv[n];
        }
        __syncthreads();
    }
#pragma unroll
    for (int m = 0; m < 8; m++) {
        int jj = o0 + m;
        float bj = b1[jj];
        float* outp = hout + ((size_t)b * CC + jj) * NN + x0 + xf0;
#pragma unroll
        for (int n = 0; n < 8; n++) outp[n] = gelu_exact(acc[m][n] + bj);
    }
}
__global__ void fc2_kernel(const float* __restrict__ hin, float* __restrict__ out,
                           const float* __restrict__ w2, const float* __restrict__ b2,
                           const float* __restrict__ mask) {
    __shared__ float ws[128];
    int x0 = blockIdx.x * 128, b = blockIdx.y;
    ws[threadIdx.x] = w2[threadIdx.x];
    __syncthreads();
    int x = x0 + threadIdx.x;
    float acc = 0.f;
#pragma unroll 8
    for (int j = 0; j < 128; j++) acc += hin[((size_t)b * CC + j) * NN + x] * ws[j];
    out[b * NN + x] = (acc + b2[0]) * mask[b * NN + x];
}

// ---------------- launch ----------------
extern "C" void kernel_launch(void* const* d_in, const int* in_sizes, int n_in,
                              void* d_out, int out_size) {
    const float* x     = (const float*)d_in[0];
    const float* nodes = (const float*)d_in[1];
    const float* mask  = (const float*)d_in[2];
    const float* nw    = (const float*)d_in[3];
    const float* modes = (const float*)d_in[4];
    const float* fc0w  = (const float*)d_in[5];
    const float* fc0b  = (const float*)d_in[6];
    const float* wc    = (const float*)d_in[7];
    const float* ws_   = (const float*)d_in[8];
    const float* w0    = (const float*)d_in[9];
    const float* convw = (const float*)d_in[10];
    const float* convb = (const float*)d_in[11];
    const float* fc1w  = (const float*)d_in[12];
    const float* fc1b  = (const float*)d_in[13];
    const float* fc2w  = (const float*)d_in[14];
    const float* fc2b  = (const float*)d_in[15];
    float* out = (float*)d_out;

    float *hA, *hB, *pcp, *psp;
    bf *wbch, *wbcl, *wbsh, *wbsl, *nch, *ncl;
    cudaGetSymbolAddress((void**)&hA, g_h);
    cudaGetSymbolAddress((void**)&hB, g_h2);
    cudaGetSymbolAddress((void**)&pcp, g_pc);
    cudaGetSymbolAddress((void**)&psp, g_ps);
    cudaGetSymbolAddress((void**)&wbch, g_wbc_hi);
    cudaGetSymbolAddress((void**)&wbcl, g_wbc_lo);
    cudaGetSymbolAddress((void**)&wbsh, g_wbs_hi);
    cudaGetSymbolAddress((void**)&wbsl, g_wbs_lo);
    cudaGetSymbolAddress((void**)&nch, g_nch);
    cudaGetSymbolAddress((void**)&ncl, g_ncl);

    bases_nk_kernel<<<(BB*NN*KK)/256, 256>>>(nodes, mask, modes);
    basesT_kernel<<<dim3(NN/32, BB), 256>>>(nodes, mask, nw, modes);
    fc0_kernel<<<(BB*CC*NN)/256, 256>>>(x, fc0w, fc0b);
    split_convw<<<(LL*CC*CC)/256, 256>>>(convw);

    float* cur = hA;
    float* nxt = hB;
    for (int l = 0; l < LL; l++) {
        split_h_kernel<<<(BB*CC*NN)/256, 256>>>(cur);
        trans_split<<<dim3(NN/32, 4*BB), 256>>>(cur);
        gemm_fwd<<<dim3(NSPLIT, BB), 256>>>(wbch, wbcl, pcp);
        gemm_fwd<<<dim3(NSPLIT, BB), 256>>>(wbsh, wbsl, psp);
        reduce_kernel<<<(BB*CC*KK)/256, 256>>>();
        x0_kernel<<<dim3(CC, BB), 256>>>(cur, nw, mask);
        f0_kernel<<<BB, CC>>>(w0, l);
        mix_kernel<<<dim3(CC, BB), KK>>>(wc, ws_, l);
        inv3<<<dim3(NN/128, BB), 256>>>(nch, ncl, nxt, convb, mask, l, (l != LL-1) ? 1 : 0);
        float* t = cur; cur = nxt; nxt = t;
    }
    fc1_kernel<<<dim3(NN/128, BB), 256>>>(cur, nxt, fc1w, fc1b);
    fc2_kernel<<<dim3(NN/128, BB), 128>>>(nxt, out, fc2w, fc2b, mask);
}

// round 8
// speedup vs baseline: 1.7041x; 1.0751x over previous
#include <cuda_runtime.h>
#include <cuda_bf16.h>
#include <cstdint>
#include <math.h>

#define BB 8
#define NN 16384
#define KK 128
#define CC 128
#define LL 4
#define NSPLIT 32
#define XS (NN / NSPLIT)   // 512
#define PAD 40

typedef __nv_bfloat16 bf;

// ---------------- device scratch ----------------
__device__ bf g_bc_hi[BB*NN*KK], g_bc_lo[BB*NN*KK];     // bases_c [b][n][k] split
__device__ bf g_bs_hi[BB*NN*KK], g_bs_lo[BB*NN*KK];     // bases_s [b][n][k] split
__device__ bf g_wbc_hi[BB*KK*NN], g_wbc_lo[BB*KK*NN];   // (cos*mask*nw)^T [b][k][n] split
__device__ bf g_wbs_hi[BB*KK*NN], g_wbs_lo[BB*KK*NN];
__device__ bf g_hcnh[2][BB*CC*NN], g_hcnl[2][BB*CC*NN]; // split h [b][c][n], double buffer
__device__ bf g_nch[BB*NN*CC], g_ncl[BB*NN*CC];         // split h [b][n][c]
__device__ float g_pc[NSPLIT*BB*CC*KK], g_ps[NSPLIT*BB*CC*KK];
__device__ float g_xc[BB*CC*KK], g_xs[BB*CC*KK];
__device__ float g_x0v[BB*CC], g_f0v[BB*CC];
__device__ bf g_fcw_hi[BB*CC*KK], g_fcw_lo[BB*CC*KK];   // 2*f_c_hat split
__device__ bf g_fsw_hi[BB*CC*KK], g_fsw_lo[BB*CC*KK];   // -2*f_s_hat split
__device__ bf g_cw_hi[LL*CC*CC], g_cw_lo[LL*CC*CC];     // conv_w split [l][o][i]
__device__ bf g_w1t_hi[CC*CC], g_w1t_lo[CC*CC];         // fc1_w^T split [j][c]
__device__ float g_fc1out[BB*CC*NN];

// ---------------- helpers ----------------
__device__ __forceinline__ void split_bf(float v, bf& h, bf& l) {
    h = __float2bfloat16(v);
    l = __float2bfloat16(v - __bfloat162float(h));
}
__device__ __forceinline__ float gelu_exact(float v) {
    return 0.5f * v * (1.0f + erff(v * 0.70710678118654752f));
}
#define MMA(d, a0, a1, a2, a3, b0, b1) \
    asm volatile("mma.sync.aligned.m16n8k16.row.col.f32.bf16.bf16.f32 " \
        "{%0,%1,%2,%3}, {%4,%5,%6,%7}, {%8,%9}, {%0,%1,%2,%3};" \
        : "+f"((d)[0]), "+f"((d)[1]), "+f"((d)[2]), "+f"((d)[3]) \
        : "r"(a0), "r"(a1), "r"(a2), "r"(a3), "r"(b0), "r"(b1))

__device__ __forceinline__ void cp_tile(bf* dst, const bf* __restrict__ src, size_t ldm, int tid) {
#pragma unroll
    for (int j = 0; j < 2; j++) {
        int idx = tid + j * 256;
        int row = idx >> 2, q = idx & 3;
        *(uint4*)(dst + row * PAD + q * 8) = *(const uint4*)(src + (size_t)row * ldm + q * 8);
    }
}

__device__ __forceinline__ void gemm_chunk(const bf* Ah, const bf* Al, const bf* Bh, const bf* Bl,
                                           float acc[4][4][4], int g, int tg, int m0, int n0) {
#pragma unroll
    for (int ks = 0; ks < 32; ks += 16) {
        uint32_t bh[4][2], bl[4][2];
#pragma unroll
        for (int nt = 0; nt < 4; nt++) {
            const bf* p = Bh + (n0 + nt * 8 + g) * PAD + ks + tg * 2;
            bh[nt][0] = *(const uint32_t*)p;
            bh[nt][1] = *(const uint32_t*)(p + 8);
            const bf* q = Bl + (n0 + nt * 8 + g) * PAD + ks + tg * 2;
            bl[nt][0] = *(const uint32_t*)q;
            bl[nt][1] = *(const uint32_t*)(q + 8);
        }
#pragma unroll
        for (int mt = 0; mt < 4; mt++) {
            const bf* p = Ah + (m0 + mt * 16 + g) * PAD + ks + tg * 2;
            uint32_t ah0 = *(const uint32_t*)p;
            uint32_t ah1 = *(const uint32_t*)(p + 8 * PAD);
            uint32_t ah2 = *(const uint32_t*)(p + 8);
            uint32_t ah3 = *(const uint32_t*)(p + 8 * PAD + 8);
            const bf* q = Al + (m0 + mt * 16 + g) * PAD + ks + tg * 2;
            uint32_t al0 = *(const uint32_t*)q;
            uint32_t al1 = *(const uint32_t*)(q + 8 * PAD);
            uint32_t al2 = *(const uint32_t*)(q + 8);
            uint32_t al3 = *(const uint32_t*)(q + 8 * PAD + 8);
#pragma unroll
            for (int nt = 0; nt < 4; nt++) {
                MMA(acc[mt][nt], ah0, ah1, ah2, ah3, bh[nt][0], bh[nt][1]);
                MMA(acc[mt][nt], ah0, ah1, ah2, ah3, bl[nt][0], bl[nt][1]);
                MMA(acc[mt][nt], al0, al1, al2, al3, bh[nt][0], bh[nt][1]);
            }
        }
    }
}

// ---------------- producers ----------------
__global__ void bases_nk_kernel(const float* __restrict__ nodes, const float* __restrict__ mask,
                                const float* __restrict__ modes) {
    int gid = blockIdx.x * blockDim.x + threadIdx.x;
    int k = gid & (KK - 1);
    int bn = gid >> 7;
    float m = mask[bn];
    float t = nodes[bn*2] * __ldg(&modes[k*2]) + nodes[bn*2+1] * __ldg(&modes[k*2+1]);
    float s, c; sincosf(t, &s, &c);
    bf h, l;
    split_bf(c * m, h, l); g_bc_hi[gid] = h; g_bc_lo[gid] = l;
    split_bf(s * m, h, l); g_bs_hi[gid] = h; g_bs_lo[gid] = l;
}
__global__ void basesT_kernel(const float* __restrict__ nodes, const float* __restrict__ mask,
                              const float* __restrict__ nw, const float* __restrict__ modes) {
    __shared__ uint32_t Tc[KK*32], Tsn[KK*32];
    int n0 = blockIdx.x * 32, b = blockIdx.y, tid = threadIdx.x;
    for (int idx = tid; idx < KK*32; idx += 256) {
        int n = idx & 31, k = idx >> 5;
        int bn = b * NN + n0 + n;
        float f = mask[bn] * nw[bn];
        float t = nodes[bn*2] * __ldg(&modes[k*2]) + nodes[bn*2+1] * __ldg(&modes[k*2+1]);
        float s, c; sincosf(t, &s, &c);
        bf h, l;
        split_bf(c * f, h, l);
        Tc[idx] = (uint32_t)__bfloat16_as_ushort(h) | ((uint32_t)__bfloat16_as_ushort(l) << 16);
        split_bf(s * f, h, l);
        Tsn[idx] = (uint32_t)__bfloat16_as_ushort(h) | ((uint32_t)__bfloat16_as_ushort(l) << 16);
    }
    __syncthreads();
    for (int idx = tid; idx < KK*32; idx += 256) {
        int n = idx & 31, k = idx >> 5;
        size_t o = ((size_t)(b * KK + k)) * NN + n0 + n;
        uint32_t vc = Tc[idx], vs = Tsn[idx];
        g_wbc_hi[o] = __ushort_as_bfloat16((unsigned short)(vc & 0xffff));
        g_wbc_lo[o] = __ushort_as_bfloat16((unsigned short)(vc >> 16));
        g_wbs_hi[o] = __ushort_as_bfloat16((unsigned short)(vs & 0xffff));
        g_wbs_lo[o] = __ushort_as_bfloat16((unsigned short)(vs >> 16));
    }
}
// fc0 -> split hcn directly
__global__ void fc0_kernel(const float* __restrict__ x, const float* __restrict__ w,
                           const float* __restrict__ bias,
                           bf* __restrict__ ohh, bf* __restrict__ ohl) {
    int gid = blockIdx.x * blockDim.x + threadIdx.x;   // (b,c,n), n fastest
    int n = gid & (NN-1), c = (gid >> 14) & (CC-1), b = gid >> 21;
    const float* xp = x + ((size_t)b*NN + n)*3;
    float v = bias[c] + xp[0]*w[c] + xp[1]*w[CC+c] + xp[2]*w[2*CC+c];
    bf hi, lo; split_bf(v, hi, lo);
    ohh[gid] = hi; ohl[gid] = lo;
}
__global__ void split_weights_kernel(const float* __restrict__ convw, const float* __restrict__ fc1w) {
    int gid = blockIdx.x * blockDim.x + threadIdx.x;   // LL*CC*CC
    bf h, l;
    split_bf(convw[gid], h, l);
    g_cw_hi[gid] = h; g_cw_lo[gid] = l;
    if (gid < CC*CC) {
        int j = gid >> 7, c = gid & 127;
        split_bf(fc1w[c*CC + j], h, l);   // transpose -> [j][c]
        g_w1t_hi[gid] = h; g_w1t_lo[gid] = l;
    }
}
// transpose: split hcn [b][c][n] -> split hnc [b][n][c]  (moves hi/lo pair exactly)
__global__ void trans_split(const bf* __restrict__ hh, const bf* __restrict__ hl) {
    __shared__ uint32_t T[32][33];
    int n0 = blockIdx.x * 32;
    int cb = blockIdx.y & 3;
    int b = blockIdx.y >> 2;
    int c0 = cb * 32;
    int tx = threadIdx.x & 31, ty = threadIdx.x >> 5;   // 32 x 8
#pragma unroll
    for (int i = 0; i < 4; i++) {
        int c = c0 + ty + i * 8;
        size_t off = ((size_t)b * CC + c) * NN + n0 + tx;
        T[ty + i * 8][tx] = (uint32_t)__bfloat16_as_ushort(hh[off])
                          | ((uint32_t)__bfloat16_as_ushort(hl[off]) << 16);
    }
    __syncthreads();
#pragma unroll
    for (int i = 0; i < 4; i++) {
        int n = n0 + ty + i * 8;
        uint32_t v = T[tx][ty + i * 8];
        size_t o = ((size_t)b * NN + n) * CC + c0 + tx;
        g_nch[o] = __ushort_as_bfloat16((unsigned short)(v & 0xffff));
        g_ncl[o] = __ushort_as_bfloat16((unsigned short)(v >> 16));
    }
}

// ---------------- forward projection GEMM (MMA) ----------------
__global__ __launch_bounds__(256) void gemm_fwd(const bf* __restrict__ Ahg, const bf* __restrict__ Alg,
                                                const bf* __restrict__ Bhg, const bf* __restrict__ Blg,
                                                float* __restrict__ outp) {
    __shared__ bf Ah[128*PAD], Al[128*PAD], Bh[128*PAD], Bl[128*PAD];
    int split = blockIdx.x, b = blockIdx.y;
    int tid = threadIdx.x, w = tid >> 5, lane = tid & 31, g = lane >> 2, tg = lane & 3;
    int m0 = (w & 1) * 64, n0 = (w >> 1) * 32;
    const bf* As_h = Ahg + (size_t)b * CC * NN;
    const bf* As_l = Alg + (size_t)b * CC * NN;
    const bf* Bs_h = Bhg + (size_t)b * KK * NN;
    const bf* Bs_l = Blg + (size_t)b * KK * NN;
    float acc[4][4][4];
#pragma unroll
    for (int i = 0; i < 4; i++)
#pragma unroll
        for (int j = 0; j < 4; j++)
#pragma unroll
            for (int q = 0; q < 4; q++) acc[i][j][q] = 0.f;

    for (int ch = 0; ch < XS / 32; ch++) {
        int x0 = split * XS + ch * 32;
        cp_tile(Ah, As_h + x0, NN, tid);
        cp_tile(Al, As_l + x0, NN, tid);
        cp_tile(Bh, Bs_h + x0, NN, tid);
        cp_tile(Bl, Bs_l + x0, NN, tid);
        __syncthreads();
        gemm_chunk(Ah, Al, Bh, Bl, acc, g, tg, m0, n0);
        __syncthreads();
    }
    float* pp = outp + (size_t)(split * BB + b) * CC * KK;
#pragma unroll
    for (int mt = 0; mt < 4; mt++) {
        int r0 = m0 + mt * 16 + g;
#pragma unroll
        for (int nt = 0; nt < 4; nt++) {
            int n = n0 + nt * 8 + tg * 2;
            *(float2*)&pp[r0 * KK + n] = make_float2(acc[mt][nt][0], acc[mt][nt][1]);
            *(float2*)&pp[(r0 + 8) * KK + n] = make_float2(acc[mt][nt][2], acc[mt][nt][3]);
        }
    }
}

// ---------------- fused inverse: 2fc@bc^T - 2fs@bs^T + conv_w@h; epilogue -> split hcn ----------------
__global__ __launch_bounds__(256) void inv3(const bf* __restrict__ hnc_hi, const bf* __restrict__ hnc_lo,
                                            bf* __restrict__ ohh, bf* __restrict__ ohl,
                                            const float* __restrict__ convb,
                                            const float* __restrict__ mask,
                                            int l, int apply_gelu) {
    __shared__ bf Ah[128*PAD], Al[128*PAD], Bh[128*PAD], Bl[128*PAD];
    int xb = blockIdx.x * 128, b = blockIdx.y;
    int tid = threadIdx.x, w = tid >> 5, lane = tid & 31, g = lane >> 2, tg = lane & 3;
    int m0 = (w & 1) * 64, n0 = (w >> 1) * 32;
    float acc[4][4][4];
#pragma unroll
    for (int i = 0; i < 4; i++)
#pragma unroll
        for (int j = 0; j < 4; j++)
#pragma unroll
            for (int q = 0; q < 4; q++) acc[i][j][q] = 0.f;

    for (int pass = 0; pass < 3; pass++) {
        const bf *pAh, *pAl, *pBh, *pBl;
        if (pass == 0) {
            pAh = g_fcw_hi + (size_t)b*CC*KK; pAl = g_fcw_lo + (size_t)b*CC*KK;
            pBh = g_bc_hi + ((size_t)b*NN + xb)*KK; pBl = g_bc_lo + ((size_t)b*NN + xb)*KK;
        } else if (pass == 1) {
            pAh = g_fsw_hi + (size_t)b*CC*KK; pAl = g_fsw_lo + (size_t)b*CC*KK;
            pBh = g_bs_hi + ((size_t)b*NN + xb)*KK; pBl = g_bs_lo + ((size_t)b*NN + xb)*KK;
        } else {
            pAh = g_cw_hi + (size_t)l*CC*CC; pAl = g_cw_lo + (size_t)l*CC*CC;
            pBh = hnc_hi + ((size_t)b*NN + xb)*CC; pBl = hnc_lo + ((size_t)b*NN + xb)*CC;
        }
        for (int ch = 0; ch < 4; ch++) {
            int k0 = ch * 32;
            cp_tile(Ah, pAh + k0, 128, tid);
            cp_tile(Al, pAl + k0, 128, tid);
            cp_tile(Bh, pBh + k0, 128, tid);
            cp_tile(Bl, pBl + k0, 128, tid);
            __syncthreads();
            gemm_chunk(Ah, Al, Bh, Bl, acc, g, tg, m0, n0);
            __syncthreads();
        }
    }
#pragma unroll
    for (int mt = 0; mt < 4; mt++) {
        int r0 = m0 + mt * 16 + g, r1 = r0 + 8;
        float cb0 = convb[l * CC + r0], f00 = g_f0v[b * CC + r0];
        float cb1 = convb[l * CC + r1], f01 = g_f0v[b * CC + r1];
#pragma unroll
        for (int nt = 0; nt < 4; nt++) {
            int n = n0 + nt * 8 + tg * 2;
            float mk0 = mask[(size_t)b * NN + xb + n];
            float mk1 = mask[(size_t)b * NN + xb + n + 1];
            float v00 = acc[mt][nt][0] + cb0 + f00 * mk0;
            float v01 = acc[mt][nt][1] + cb0 + f00 * mk1;
            float v10 = acc[mt][nt][2] + cb1 + f01 * mk0;
            float v11 = acc[mt][nt][3] + cb1 + f01 * mk1;
            if (apply_gelu) {
                v00 = gelu_exact(v00); v01 = gelu_exact(v01);
                v10 = gelu_exact(v10); v11 = gelu_exact(v11);
            }
            bf h00, l00, h01, l01, h10, l10, h11, l11;
            split_bf(v00, h00, l00); split_bf(v01, h01, l01);
            split_bf(v10, h10, l10); split_bf(v11, h11, l11);
            size_t o0 = ((size_t)b * CC + r0) * NN + xb + n;
            size_t o1 = ((size_t)b * CC + r1) * NN + xb + n;
            *(uint32_t*)(ohh + o0) = (uint32_t)__bfloat16_as_ushort(h00) | ((uint32_t)__bfloat16_as_ushort(h01) << 16);
            *(uint32_t*)(ohl + o0) = (uint32_t)__bfloat16_as_ushort(l00) | ((uint32_t)__bfloat16_as_ushort(l01) << 16);
            *(uint32_t*)(ohh + o1) = (uint32_t)__bfloat16_as_ushort(h10) | ((uint32_t)__bfloat16_as_ushort(h11) << 16);
            *(uint32_t*)(ohl + o1) = (uint32_t)__bfloat16_as_ushort(l10) | ((uint32_t)__bfloat16_as_ushort(l11) << 16);
        }
    }
}

// ---------------- small kernels ----------------
__global__ void reduce_kernel() {
    int gid = blockIdx.x * blockDim.x + threadIdx.x;
    float sc = 0.f, ss = 0.f;
#pragma unroll
    for (int s = 0; s < NSPLIT; s++) {
        sc += g_pc[(size_t)s * BB * CC * KK + gid];
        ss += g_ps[(size_t)s * BB * CC * KK + gid];
    }
    g_xc[gid] = sc;
    g_xs[gid] = -ss;
}
__global__ void x0_kernel(const bf* __restrict__ hh, const bf* __restrict__ hl,
                          const float* __restrict__ nw, const float* __restrict__ mask) {
    int i = blockIdx.x, b = blockIdx.y;
    const bf* rh = hh + ((size_t)b * CC + i) * NN;
    const bf* rl = hl + ((size_t)b * CC + i) * NN;
    const float* nwb = nw + b * NN;
    const float* mb = mask + b * NN;
    float acc = 0.f;
    for (int x = threadIdx.x; x < NN; x += 256)
        acc += (__bfloat162float(rh[x]) + __bfloat162float(rl[x])) * nwb[x] * mb[x];
    __shared__ float red[256];
    red[threadIdx.x] = acc;
    __syncthreads();
    for (int s = 128; s > 0; s >>= 1) {
        if (threadIdx.x < s) red[threadIdx.x] += red[threadIdx.x + s];
        __syncthreads();
    }
    if (threadIdx.x == 0) g_x0v[b * CC + i] = red[0];
}
__global__ void f0_kernel(const float* __restrict__ w0, int l) {
    int b = blockIdx.x, o = threadIdx.x;
    __shared__ float xs[CC];
    xs[o] = g_x0v[b * CC + o];
    __syncthreads();
    const float* w = w0 + (size_t)l * CC * CC;
    float acc = 0.f;
#pragma unroll 8
    for (int i = 0; i < CC; i++) acc += xs[i] * w[i * CC + o];
    g_f0v[b * CC + o] = acc;
}
__global__ void mix_kernel(const float* __restrict__ wc, const float* __restrict__ ws, int l) {
    int o = blockIdx.x, b = blockIdx.y, k = threadIdx.x;
    const float* wcl = wc + (size_t)l * CC * CC * KK;
    const float* wsl = ws + (size_t)l * CC * CC * KK;
    float fcA = 0.f, fsA = 0.f;
#pragma unroll 4
    for (int i = 0; i < CC; i++) {
        float xc = g_xc[(b * CC + i) * KK + k];
        float xv = g_xs[(b * CC + i) * KK + k];
        float wcv = wcl[((size_t)i * CC + o) * KK + k];
        float wsv = wsl[((size_t)i * CC + o) * KK + k];
        fcA += xc * wcv - xv * wsv;
        fsA += xv * wcv + xc * wsv;
    }
    int idx = (b * CC + o) * KK + k;
    bf h, l2;
    split_bf(2.0f * fcA, h, l2);  g_fcw_hi[idx] = h; g_fcw_lo[idx] = l2;
    split_bf(-2.0f * fsA, h, l2); g_fsw_hi[idx] = h; g_fsw_lo[idx] = l2;
}

// ---------------- fc1 (MMA) + fc2 ----------------
__global__ __launch_bounds__(256) void fc1_mma(const bf* __restrict__ hnc_hi, const bf* __restrict__ hnc_lo,
                                               const float* __restrict__ b1) {
    __shared__ bf Ah[128*PAD], Al[128*PAD], Bh[128*PAD], Bl[128*PAD];
    int xb = blockIdx.x * 128, b = blockIdx.y;
    int tid = threadIdx.x, w = tid >> 5, lane = tid & 31, g = lane >> 2, tg = lane & 3;
    int m0 = (w & 1) * 64, n0 = (w >> 1) * 32;
    const bf* pBh = hnc_hi + ((size_t)b * NN + xb) * CC;
    const bf* pBl = hnc_lo + ((size_t)b * NN + xb) * CC;
    float acc[4][4][4];
#pragma unroll
    for (int i = 0; i < 4; i++)
#pragma unroll
        for (int j = 0; j < 4; j++)
#pragma unroll
            for (int q = 0; q < 4; q++) acc[i][j][q] = 0.f;

    for (int ch = 0; ch < 4; ch++) {
        int k0 = ch * 32;
        cp_tile(Ah, g_w1t_hi + k0, 128, tid);
        cp_tile(Al, g_w1t_lo + k0, 128, tid);
        cp_tile(Bh, pBh + k0, 128, tid);
        cp_tile(Bl, pBl + k0, 128, tid);
        __syncthreads();
        gemm_chunk(Ah, Al, Bh, Bl, acc, g, tg, m0, n0);
        __syncthreads();
    }
#pragma unroll
    for (int mt = 0; mt < 4; mt++) {
        int r0 = m0 + mt * 16 + g;
        float bb0 = b1[r0], bb8 = b1[r0 + 8];
#pragma unroll
        for (int nt = 0; nt < 4; nt++) {
            int n = n0 + nt * 8 + tg * 2;
            float* p0 = g_fc1out + ((size_t)b * CC + r0) * NN + xb + n;
            float* p1 = g_fc1out + ((size_t)b * CC + r0 + 8) * NN + xb + n;
            *(float2*)p0 = make_float2(gelu_exact(acc[mt][nt][0] + bb0), gelu_exact(acc[mt][nt][1] + bb0));
            *(float2*)p1 = make_float2(gelu_exact(acc[mt][nt][2] + bb8), gelu_exact(acc[mt][nt][3] + bb8));
        }
    }
}
__global__ void fc2_kernel(const float* __restrict__ hin, float* __restrict__ out,
                           const float* __restrict__ w2, const float* __restrict__ b2,
                           const float* __restrict__ mask) {
    __shared__ float ws[128];
    int x0 = blockIdx.x * 128, b = blockIdx.y;
    ws[threadIdx.x] = w2[threadIdx.x];
    __syncthreads();
    int x = x0 + threadIdx.x;
    float acc = 0.f;
#pragma unroll 8
    for (int j = 0; j < 128; j++) acc += hin[((size_t)b * CC + j) * NN + x] * ws[j];
    out[b * NN + x] = (acc + b2[0]) * mask[b * NN + x];
}

// ---------------- launch ----------------
extern "C" void kernel_launch(void* const* d_in, const int* in_sizes, int n_in,
                              void* d_out, int out_size) {
    const float* x     = (const float*)d_in[0];
    const float* nodes = (const float*)d_in[1];
    const float* mask  = (const float*)d_in[2];
    const float* nw    = (const float*)d_in[3];
    const float* modes = (const float*)d_in[4];
    const float* fc0w  = (const float*)d_in[5];
    const float* fc0b  = (const float*)d_in[6];
    const float* wc    = (const float*)d_in[7];
    const float* ws_   = (const float*)d_in[8];
    const float* w0    = (const float*)d_in[9];
    const float* convw = (const float*)d_in[10];
    const float* convb = (const float*)d_in[11];
    const float* fc1w  = (const float*)d_in[12];
    const float* fc1b  = (const float*)d_in[13];
    const float* fc2w  = (const float*)d_in[14];
    const float* fc2b  = (const float*)d_in[15];
    float* out = (float*)d_out;

    float *pcp, *psp, *f1p;
    bf *wbch, *wbcl, *wbsh, *wbsl, *nch, *ncl, *hh0, *hl0;
    cudaGetSymbolAddress((void**)&pcp, g_pc);
    cudaGetSymbolAddress((void**)&psp, g_ps);
    cudaGetSymbolAddress((void**)&f1p, g_fc1out);
    cudaGetSymbolAddress((void**)&wbch, g_wbc_hi);
    cudaGetSymbolAddress((void**)&wbcl, g_wbc_lo);
    cudaGetSymbolAddress((void**)&wbsh, g_wbs_hi);
    cudaGetSymbolAddress((void**)&wbsl, g_wbs_lo);
    cudaGetSymbolAddress((void**)&nch, g_nch);
    cudaGetSymbolAddress((void**)&ncl, g_ncl);
    cudaGetSymbolAddress((void**)&hh0, g_hcnh);
    cudaGetSymbolAddress((void**)&hl0, g_hcnl);
    bf* hh1 = hh0 + (size_t)BB*CC*NN;
    bf* hl1 = hl0 + (size_t)BB*CC*NN;

    bases_nk_kernel<<<(BB*NN*KK)/256, 256>>>(nodes, mask, modes);
    basesT_kernel<<<dim3(NN/32, BB), 256>>>(nodes, mask, nw, modes);
    fc0_kernel<<<(BB*CC*NN)/256, 256>>>(x, fc0w, fc0b, hh0, hl0);
    split_weights_kernel<<<(LL*CC*CC)/256, 256>>>(convw, fc1w);

    bf *ch = hh0, *cl = hl0, *oh = hh1, *ol = hl1;
    for (int l = 0; l < LL; l++) {
        trans_split<<<dim3(NN/32, 4*BB), 256>>>(ch, cl);
        gemm_fwd<<<dim3(NSPLIT, BB), 256>>>(ch, cl, wbch, wbcl, pcp);
        gemm_fwd<<<dim3(NSPLIT, BB), 256>>>(ch, cl, wbsh, wbsl, psp);
        reduce_kernel<<<(BB*CC*KK)/256, 256>>>();
        x0_kernel<<<dim3(CC, BB), 256>>>(ch, cl, nw, mask);
        f0_kernel<<<BB, CC>>>(w0, l);
        mix_kernel<<<dim3(CC, BB), KK>>>(wc, ws_, l);
        inv3<<<dim3(NN/128, BB), 256>>>(nch, ncl, oh, ol, convb, mask, l, (l != LL-1) ? 1 : 0);
        bf* t;
        t = ch; ch = oh; oh = t;
        t = cl; cl = ol; ol = t;
    }
    trans_split<<<dim3(NN/32, 4*BB), 256>>>(ch, cl);
    fc1_mma<<<dim3(NN/128, BB), 256>>>(nch, ncl, fc1b);
    fc2_kernel<<<dim3(NN/128, BB), 128>>>(f1p, out, fc2w, fc2b, mask);
}

// round 9
// speedup vs baseline: 2.1034x; 1.2343x over previous
#include <cuda_runtime.h>
#include <cuda_bf16.h>
#include <cstdint>
#include <math.h>

#define BB 8
#define NN 16384
#define KK 128
#define CC 128
#define LL 4
#define NSPLIT 32
#define XS (NN / NSPLIT)   // 512
#define PAD 40

typedef __nv_bfloat16 bf;

// ---------------- device scratch ----------------
__device__ bf g_bc[BB*NN*KK];                            // bases_c [b][n][k] bf16
__device__ bf g_bs[BB*NN*KK];                            // bases_s [b][n][k] bf16
__device__ bf g_wbc[BB*KK*NN];                           // (cos*mask*nw)^T [b][k][n] bf16
__device__ bf g_wbs[BB*KK*NN];
__device__ bf g_hcnh[2][BB*CC*NN], g_hcnl[2][BB*CC*NN]; // split h [b][c][n], double buffer
__device__ bf g_nch[BB*NN*CC], g_ncl[BB*NN*CC];         // split h [b][n][c]
__device__ float g_pc[NSPLIT*BB*CC*KK], g_ps[NSPLIT*BB*CC*KK];
__device__ float g_xc[BB*CC*KK], g_xs[BB*CC*KK];
__device__ float g_x0v[BB*CC], g_f0v[BB*CC];
__device__ bf g_fcw[BB*CC*KK];                           // 2*f_c_hat bf16
__device__ bf g_fsw[BB*CC*KK];                           // -2*f_s_hat bf16
__device__ bf g_cw_hi[LL*CC*CC], g_cw_lo[LL*CC*CC];     // conv_w split [l][o][i]
__device__ bf g_w1t_hi[CC*CC], g_w1t_lo[CC*CC];         // fc1_w^T split [j][c]
__device__ float g_fc1out[BB*CC*NN];

// ---------------- helpers ----------------
__device__ __forceinline__ void split_bf(float v, bf& h, bf& l) {
    h = __float2bfloat16(v);
    l = __float2bfloat16(v - __bfloat162float(h));
}
__device__ __forceinline__ float gelu_exact(float v) {
    return 0.5f * v * (1.0f + erff(v * 0.70710678118654752f));
}
#define MMA(d, a0, a1, a2, a3, b0, b1) \
    asm volatile("mma.sync.aligned.m16n8k16.row.col.f32.bf16.bf16.f32 " \
        "{%0,%1,%2,%3}, {%4,%5,%6,%7}, {%8,%9}, {%0,%1,%2,%3};" \
        : "+f"((d)[0]), "+f"((d)[1]), "+f"((d)[2]), "+f"((d)[3]) \
        : "r"(a0), "r"(a1), "r"(a2), "r"(a3), "r"(b0), "r"(b1))

__device__ __forceinline__ void cp_tile(bf* dst, const bf* __restrict__ src, size_t ldm, int tid) {
#pragma unroll
    for (int j = 0; j < 2; j++) {
        int idx = tid + j * 256;
        int row = idx >> 2, q = idx & 3;
        *(uint4*)(dst + row * PAD + q * 8) = *(const uint4*)(src + (size_t)row * ldm + q * 8);
    }
}

// single-term: acc += A*B (plain bf16, spectral path)
__device__ __forceinline__ void gemm_chunk1(const bf* A, const bf* B,
                                            float acc[4][4][4], int g, int tg, int m0, int n0) {
#pragma unroll
    for (int ks = 0; ks < 32; ks += 16) {
        uint32_t bh[4][2];
#pragma unroll
        for (int nt = 0; nt < 4; nt++) {
            const bf* p = B + (n0 + nt * 8 + g) * PAD + ks + tg * 2;
            bh[nt][0] = *(const uint32_t*)p;
            bh[nt][1] = *(const uint32_t*)(p + 8);
        }
#pragma unroll
        for (int mt = 0; mt < 4; mt++) {
            const bf* p = A + (m0 + mt * 16 + g) * PAD + ks + tg * 2;
            uint32_t a0 = *(const uint32_t*)p;
            uint32_t a1 = *(const uint32_t*)(p + 8 * PAD);
            uint32_t a2 = *(const uint32_t*)(p + 8);
            uint32_t a3 = *(const uint32_t*)(p + 8 * PAD + 8);
#pragma unroll
            for (int nt = 0; nt < 4; nt++)
                MMA(acc[mt][nt], a0, a1, a2, a3, bh[nt][0], bh[nt][1]);
        }
    }
}

// 3-term split: acc += Ah*Bh + Ah*Bl + Al*Bh (precision-critical path)
__device__ __forceinline__ void gemm_chunk3(const bf* Ah, const bf* Al, const bf* Bh, const bf* Bl,
                                            float acc[4][4][4], int g, int tg, int m0, int n0) {
#pragma unroll
    for (int ks = 0; ks < 32; ks += 16) {
        uint32_t bh[4][2], bl[4][2];
#pragma unroll
        for (int nt = 0; nt < 4; nt++) {
            const bf* p = Bh + (n0 + nt * 8 + g) * PAD + ks + tg * 2;
            bh[nt][0] = *(const uint32_t*)p;
            bh[nt][1] = *(const uint32_t*)(p + 8);
            const bf* q = Bl + (n0 + nt * 8 + g) * PAD + ks + tg * 2;
            bl[nt][0] = *(const uint32_t*)q;
            bl[nt][1] = *(const uint32_t*)(q + 8);
        }
#pragma unroll
        for (int mt = 0; mt < 4; mt++) {
            const bf* p = Ah + (m0 + mt * 16 + g) * PAD + ks + tg * 2;
            uint32_t ah0 = *(const uint32_t*)p;
            uint32_t ah1 = *(const uint32_t*)(p + 8 * PAD);
            uint32_t ah2 = *(const uint32_t*)(p + 8);
            uint32_t ah3 = *(const uint32_t*)(p + 8 * PAD + 8);
            const bf* q = Al + (m0 + mt * 16 + g) * PAD + ks + tg * 2;
            uint32_t al0 = *(const uint32_t*)q;
            uint32_t al1 = *(const uint32_t*)(q + 8 * PAD);
            uint32_t al2 = *(const uint32_t*)(q + 8);
            uint32_t al3 = *(const uint32_t*)(q + 8 * PAD + 8);
#pragma unroll
            for (int nt = 0; nt < 4; nt++) {
                MMA(acc[mt][nt], ah0, ah1, ah2, ah3, bh[nt][0], bh[nt][1]);
                MMA(acc[mt][nt], ah0, ah1, ah2, ah3, bl[nt][0], bl[nt][1]);
                MMA(acc[mt][nt], al0, al1, al2, al3, bh[nt][0], bh[nt][1]);
            }
        }
    }
}

// ---------------- producers ----------------
__global__ void bases_nk_kernel(const float* __restrict__ nodes, const float* __restrict__ mask,
                                const float* __restrict__ modes) {
    int gid = blockIdx.x * blockDim.x + threadIdx.x;
    int k = gid & (KK - 1);
    int bn = gid >> 7;
    float m = mask[bn];
    float t = nodes[bn*2] * __ldg(&modes[k*2]) + nodes[bn*2+1] * __ldg(&modes[k*2+1]);
    float s, c; sincosf(t, &s, &c);
    g_bc[gid] = __float2bfloat16(c * m);
    g_bs[gid] = __float2bfloat16(s * m);
}
__global__ void basesT_kernel(const float* __restrict__ nodes, const float* __restrict__ mask,
                              const float* __restrict__ nw, const float* __restrict__ modes) {
    __shared__ unsigned short Tc[KK*32], Tsn[KK*32];
    int n0 = blockIdx.x * 32, b = blockIdx.y, tid = threadIdx.x;
    for (int idx = tid; idx < KK*32; idx += 256) {
        int n = idx & 31, k = idx >> 5;
        int bn = b * NN + n0 + n;
        float f = mask[bn] * nw[bn];
        float t = nodes[bn*2] * __ldg(&modes[k*2]) + nodes[bn*2+1] * __ldg(&modes[k*2+1]);
        float s, c; sincosf(t, &s, &c);
        Tc[idx] = __bfloat16_as_ushort(__float2bfloat16(c * f));
        Tsn[idx] = __bfloat16_as_ushort(__float2bfloat16(s * f));
    }
    __syncthreads();
    for (int idx = tid; idx < KK*32; idx += 256) {
        int n = idx & 31, k = idx >> 5;
        size_t o = ((size_t)(b * KK + k)) * NN + n0 + n;
        g_wbc[o] = __ushort_as_bfloat16(Tc[idx]);
        g_wbs[o] = __ushort_as_bfloat16(Tsn[idx]);
    }
}
__global__ void fc0_kernel(const float* __restrict__ x, const float* __restrict__ w,
                           const float* __restrict__ bias,
                           bf* __restrict__ ohh, bf* __restrict__ ohl) {
    int gid = blockIdx.x * blockDim.x + threadIdx.x;   // (b,c,n), n fastest
    int n = gid & (NN-1), c = (gid >> 14) & (CC-1), b = gid >> 21;
    const float* xp = x + ((size_t)b*NN + n)*3;
    float v = bias[c] + xp[0]*w[c] + xp[1]*w[CC+c] + xp[2]*w[2*CC+c];
    bf hi, lo; split_bf(v, hi, lo);
    ohh[gid] = hi; ohl[gid] = lo;
}
__global__ void split_weights_kernel(const float* __restrict__ convw, const float* __restrict__ fc1w) {
    int gid = blockIdx.x * blockDim.x + threadIdx.x;   // LL*CC*CC
    bf h, l;
    split_bf(convw[gid], h, l);
    g_cw_hi[gid] = h; g_cw_lo[gid] = l;
    if (gid < CC*CC) {
        int j = gid >> 7, c = gid & 127;
        split_bf(fc1w[c*CC + j], h, l);   // transpose -> [j][c]
        g_w1t_hi[gid] = h; g_w1t_lo[gid] = l;
    }
}
// transpose: split hcn [b][c][n] -> split hnc [b][n][c]
__global__ void trans_split(const bf* __restrict__ hh, const bf* __restrict__ hl) {
    __shared__ uint32_t T[32][33];
    int n0 = blockIdx.x * 32;
    int cb = blockIdx.y & 3;
    int b = blockIdx.y >> 2;
    int c0 = cb * 32;
    int tx = threadIdx.x & 31, ty = threadIdx.x >> 5;   // 32 x 8
#pragma unroll
    for (int i = 0; i < 4; i++) {
        int c = c0 + ty + i * 8;
        size_t off = ((size_t)b * CC + c) * NN + n0 + tx;
        T[ty + i * 8][tx] = (uint32_t)__bfloat16_as_ushort(hh[off])
                          | ((uint32_t)__bfloat16_as_ushort(hl[off]) << 16);
    }
    __syncthreads();
#pragma unroll
    for (int i = 0; i < 4; i++) {
        int n = n0 + ty + i * 8;
        uint32_t v = T[tx][ty + i * 8];
        size_t o = ((size_t)b * NN + n) * CC + c0 + tx;
        g_nch[o] = __ushort_as_bfloat16((unsigned short)(v & 0xffff));
        g_ncl[o] = __ushort_as_bfloat16((unsigned short)(v >> 16));
    }
}

// ---------------- forward projection GEMM (bf16, spectral) ----------------
__global__ __launch_bounds__(256) void gemm_fwd(const bf* __restrict__ Ahg,
                                                const bf* __restrict__ Bhg,
                                                float* __restrict__ outp) {
    __shared__ bf As[128*PAD], Bs[128*PAD];
    int split = blockIdx.x, b = blockIdx.y;
    int tid = threadIdx.x, w = tid >> 5, lane = tid & 31, g = lane >> 2, tg = lane & 3;
    int m0 = (w & 1) * 64, n0 = (w >> 1) * 32;
    const bf* As_g = Ahg + (size_t)b * CC * NN;
    const bf* Bs_g = Bhg + (size_t)b * KK * NN;
    float acc[4][4][4];
#pragma unroll
    for (int i = 0; i < 4; i++)
#pragma unroll
        for (int j = 0; j < 4; j++)
#pragma unroll
            for (int q = 0; q < 4; q++) acc[i][j][q] = 0.f;

    for (int ch = 0; ch < XS / 32; ch++) {
        int x0 = split * XS + ch * 32;
        cp_tile(As, As_g + x0, NN, tid);
        cp_tile(Bs, Bs_g + x0, NN, tid);
        __syncthreads();
        gemm_chunk1(As, Bs, acc, g, tg, m0, n0);
        __syncthreads();
    }
    float* pp = outp + (size_t)(split * BB + b) * CC * KK;
#pragma unroll
    for (int mt = 0; mt < 4; mt++) {
        int r0 = m0 + mt * 16 + g;
#pragma unroll
        for (int nt = 0; nt < 4; nt++) {
            int n = n0 + nt * 8 + tg * 2;
            *(float2*)&pp[r0 * KK + n] = make_float2(acc[mt][nt][0], acc[mt][nt][1]);
            *(float2*)&pp[(r0 + 8) * KK + n] = make_float2(acc[mt][nt][2], acc[mt][nt][3]);
        }
    }
}

// ---------------- fused inverse: 2fc@bc^T - 2fs@bs^T (bf16) + conv_w@h (split); -> split hcn ----------------
__global__ __launch_bounds__(256) void inv3(const bf* __restrict__ hnc_hi, const bf* __restrict__ hnc_lo,
                                            bf* __restrict__ ohh, bf* __restrict__ ohl,
                                            const float* __restrict__ convb,
                                            const float* __restrict__ mask,
                                            int l, int apply_gelu) {
    __shared__ bf Ah[128*PAD], Al[128*PAD], Bh[128*PAD], Bl[128*PAD];
    int xb = blockIdx.x * 128, b = blockIdx.y;
    int tid = threadIdx.x, w = tid >> 5, lane = tid & 31, g = lane >> 2, tg = lane & 3;
    int m0 = (w & 1) * 64, n0 = (w >> 1) * 32;
    float acc[4][4][4];
#pragma unroll
    for (int i = 0; i < 4; i++)
#pragma unroll
        for (int j = 0; j < 4; j++)
#pragma unroll
            for (int q = 0; q < 4; q++) acc[i][j][q] = 0.f;

    // pass 0/1: plain bf16 spectral
    for (int pass = 0; pass < 2; pass++) {
        const bf* pA = (pass ? g_fsw : g_fcw) + (size_t)b*CC*KK;
        const bf* pB = (pass ? g_bs : g_bc) + ((size_t)b*NN + xb)*KK;
        for (int ch = 0; ch < 4; ch++) {
            int k0 = ch * 32;
            cp_tile(Ah, pA + k0, 128, tid);
            cp_tile(Bh, pB + k0, 128, tid);
            __syncthreads();
            gemm_chunk1(Ah, Bh, acc, g, tg, m0, n0);
            __syncthreads();
        }
    }
    // pass 2: conv (3-term split)
    {
        const bf* pAh = g_cw_hi + (size_t)l*CC*CC;
        const bf* pAl = g_cw_lo + (size_t)l*CC*CC;
        const bf* pBh = hnc_hi + ((size_t)b*NN + xb)*CC;
        const bf* pBl = hnc_lo + ((size_t)b*NN + xb)*CC;
        for (int ch = 0; ch < 4; ch++) {
            int k0 = ch * 32;
            cp_tile(Ah, pAh + k0, 128, tid);
            cp_tile(Al, pAl + k0, 128, tid);
            cp_tile(Bh, pBh + k0, 128, tid);
            cp_tile(Bl, pBl + k0, 128, tid);
            __syncthreads();
            gemm_chunk3(Ah, Al, Bh, Bl, acc, g, tg, m0, n0);
            __syncthreads();
        }
    }
#pragma unroll
    for (int mt = 0; mt < 4; mt++) {
        int r0 = m0 + mt * 16 + g, r1 = r0 + 8;
        float cb0 = convb[l * CC + r0], f00 = g_f0v[b * CC + r0];
        float cb1 = convb[l * CC + r1], f01 = g_f0v[b * CC + r1];
#pragma unroll
        for (int nt = 0; nt < 4; nt++) {
            int n = n0 + nt * 8 + tg * 2;
            float mk0 = mask[(size_t)b * NN + xb + n];
            float mk1 = mask[(size_t)b * NN + xb + n + 1];
            float v00 = acc[mt][nt][0] + cb0 + f00 * mk0;
            float v01 = acc[mt][nt][1] + cb0 + f00 * mk1;
            float v10 = acc[mt][nt][2] + cb1 + f01 * mk0;
            float v11 = acc[mt][nt][3] + cb1 + f01 * mk1;
            if (apply_gelu) {
                v00 = gelu_exact(v00); v01 = gelu_exact(v01);
                v10 = gelu_exact(v10); v11 = gelu_exact(v11);
            }
            bf h00, l00, h01, l01, h10, l10, h11, l11;
            split_bf(v00, h00, l00); split_bf(v01, h01, l01);
            split_bf(v10, h10, l10); split_bf(v11, h11, l11);
            size_t o0 = ((size_t)b * CC + r0) * NN + xb + n;
            size_t o1 = ((size_t)b * CC + r1) * NN + xb + n;
            *(uint32_t*)(ohh + o0) = (uint32_t)__bfloat16_as_ushort(h00) | ((uint32_t)__bfloat16_as_ushort(h01) << 16);
            *(uint32_t*)(ohl + o0) = (uint32_t)__bfloat16_as_ushort(l00) | ((uint32_t)__bfloat16_as_ushort(l01) << 16);
            *(uint32_t*)(ohh + o1) = (uint32_t)__bfloat16_as_ushort(h10) | ((uint32_t)__bfloat16_as_ushort(h11) << 16);
            *(uint32_t*)(ohl + o1) = (uint32_t)__bfloat16_as_ushort(l10) | ((uint32_t)__bfloat16_as_ushort(l11) << 16);
        }
    }
}

// ---------------- small kernels ----------------
__global__ void reduce_kernel() {
    int gid = blockIdx.x * blockDim.x + threadIdx.x;
    float sc = 0.f, ss = 0.f;
#pragma unroll
    for (int s = 0; s < NSPLIT; s++) {
        sc += g_pc[(size_t)s * BB * CC * KK + gid];
        ss += g_ps[(size_t)s * BB * CC * KK + gid];
    }
    g_xc[gid] = sc;
    g_xs[gid] = -ss;
}
__global__ void x0_kernel(const bf* __restrict__ hh,
                          const float* __restrict__ nw, const float* __restrict__ mask) {
    int i = blockIdx.x, b = blockIdx.y;
    const bf* rh = hh + ((size_t)b * CC + i) * NN;
    const float* nwb = nw + b * NN;
    const float* mb = mask + b * NN;
    float acc = 0.f;
    for (int x = threadIdx.x; x < NN; x += 256)
        acc += __bfloat162float(rh[x]) * nwb[x] * mb[x];
    __shared__ float red[256];
    red[threadIdx.x] = acc;
    __syncthreads();
    for (int s = 128; s > 0; s >>= 1) {
        if (threadIdx.x < s) red[threadIdx.x] += red[threadIdx.x + s];
        __syncthreads();
    }
    if (threadIdx.x == 0) g_x0v[b * CC + i] = red[0];
}
__global__ void f0_kernel(const float* __restrict__ w0, int l) {
    int b = blockIdx.x, o = threadIdx.x;
    __shared__ float xs[CC];
    xs[o] = g_x0v[b * CC + o];
    __syncthreads();
    const float* w = w0 + (size_t)l * CC * CC;
    float acc = 0.f;
#pragma unroll 8
    for (int i = 0; i < CC; i++) acc += xs[i] * w[i * CC + o];
    g_f0v[b * CC + o] = acc;
}
__global__ void mix_kernel(const float* __restrict__ wc, const float* __restrict__ ws, int l) {
    int o = blockIdx.x, b = blockIdx.y, k = threadIdx.x;
    const float* wcl = wc + (size_t)l * CC * CC * KK;
    const float* wsl = ws + (size_t)l * CC * CC * KK;
    float fcA = 0.f, fsA = 0.f;
#pragma unroll 4
    for (int i = 0; i < CC; i++) {
        float xc = g_xc[(b * CC + i) * KK + k];
        float xv = g_xs[(b * CC + i) * KK + k];
        float wcv = wcl[((size_t)i * CC + o) * KK + k];
        float wsv = wsl[((size_t)i * CC + o) * KK + k];
        fcA += xc * wcv - xv * wsv;
        fsA += xv * wcv + xc * wsv;
    }
    int idx = (b * CC + o) * KK + k;
    g_fcw[idx] = __float2bfloat16(2.0f * fcA);
    g_fsw[idx] = __float2bfloat16(-2.0f * fsA);
}

// ---------------- fc1 (MMA, split) + fc2 ----------------
__global__ __launch_bounds__(256) void fc1_mma(const bf* __restrict__ hnc_hi, const bf* __restrict__ hnc_lo,
                                               const float* __restrict__ b1) {
    __shared__ bf Ah[128*PAD], Al[128*PAD], Bh[128*PAD], Bl[128*PAD];
    int xb = blockIdx.x * 128, b = blockIdx.y;
    int tid = threadIdx.x, w = tid >> 5, lane = tid & 31, g = lane >> 2, tg = lane & 3;
    int m0 = (w & 1) * 64, n0 = (w >> 1) * 32;
    const bf* pBh = hnc_hi + ((size_t)b * NN + xb) * CC;
    const bf* pBl = hnc_lo + ((size_t)b * NN + xb) * CC;
    float acc[4][4][4];
#pragma unroll
    for (int i = 0; i < 4; i++)
#pragma unroll
        for (int j = 0; j < 4; j++)
#pragma unroll
            for (int q = 0; q < 4; q++) acc[i][j][q] = 0.f;

    for (int ch = 0; ch < 4; ch++) {
        int k0 = ch * 32;
        cp_tile(Ah, g_w1t_hi + k0, 128, tid);
        cp_tile(Al, g_w1t_lo + k0, 128, tid);
        cp_tile(Bh, pBh + k0, 128, tid);
        cp_tile(Bl, pBl + k0, 128, tid);
        __syncthreads();
        gemm_chunk3(Ah, Al, Bh, Bl, acc, g, tg, m0, n0);
        __syncthreads();
    }
#pragma unroll
    for (int mt = 0; mt < 4; mt++) {
        int r0 = m0 + mt * 16 + g;
        float bb0 = b1[r0], bb8 = b1[r0 + 8];
#pragma unroll
        for (int nt = 0; nt < 4; nt++) {
            int n = n0 + nt * 8 + tg * 2;
            float* p0 = g_fc1out + ((size_t)b * CC + r0) * NN + xb + n;
            float* p1 = g_fc1out + ((size_t)b * CC + r0 + 8) * NN + xb + n;
            *(float2*)p0 = make_float2(gelu_exact(acc[mt][nt][0] + bb0), gelu_exact(acc[mt][nt][1] + bb0));
            *(float2*)p1 = make_float2(gelu_exact(acc[mt][nt][2] + bb8), gelu_exact(acc[mt][nt][3] + bb8));
        }
    }
}
__global__ void fc2_kernel(const float* __restrict__ hin, float* __restrict__ out,
                           const float* __restrict__ w2, const float* __restrict__ b2,
                           const float* __restrict__ mask) {
    __shared__ float ws[128];
    int x0 = blockIdx.x * 128, b = blockIdx.y;
    ws[threadIdx.x] = w2[threadIdx.x];
    __syncthreads();
    int x = x0 + threadIdx.x;
    float acc = 0.f;
#pragma unroll 8
    for (int j = 0; j < 128; j++) acc += hin[((size_t)b * CC + j) * NN + x] * ws[j];
    out[b * NN + x] = (acc + b2[0]) * mask[b * NN + x];
}

// ---------------- launch ----------------
extern "C" void kernel_launch(void* const* d_in, const int* in_sizes, int n_in,
                              void* d_out, int out_size) {
    const float* x     = (const float*)d_in[0];
    const float* nodes = (const float*)d_in[1];
    const float* mask  = (const float*)d_in[2];
    const float* nw    = (const float*)d_in[3];
    const float* modes = (const float*)d_in[4];
    const float* fc0w  = (const float*)d_in[5];
    const float* fc0b  = (const float*)d_in[6];
    const float* wc    = (const float*)d_in[7];
    const float* ws_   = (const float*)d_in[8];
    const float* w0    = (const float*)d_in[9];
    const float* convw = (const float*)d_in[10];
    const float* convb = (const float*)d_in[11];
    const float* fc1w  = (const float*)d_in[12];
    const float* fc1b  = (const float*)d_in[13];
    const float* fc2w  = (const float*)d_in[14];
    const float* fc2b  = (const float*)d_in[15];
    float* out = (float*)d_out;

    float *pcp, *psp, *f1p;
    bf *wbcp, *wbsp, *nch, *ncl, *hh0, *hl0;
    cudaGetSymbolAddress((void**)&pcp, g_pc);
    cudaGetSymbolAddress((void**)&psp, g_ps);
    cudaGetSymbolAddress((void**)&f1p, g_fc1out);
    cudaGetSymbolAddress((void**)&wbcp, g_wbc);
    cudaGetSymbolAddress((void**)&wbsp, g_wbs);
    cudaGetSymbolAddress((void**)&nch, g_nch);
    cudaGetSymbolAddress((void**)&ncl, g_ncl);
    cudaGetSymbolAddress((void**)&hh0, g_hcnh);
    cudaGetSymbolAddress((void**)&hl0, g_hcnl);
    bf* hh1 = hh0 + (size_t)BB*CC*NN;
    bf* hl1 = hl0 + (size_t)BB*CC*NN;

    bases_nk_kernel<<<(BB*NN*KK)/256, 256>>>(nodes, mask, modes);
    basesT_kernel<<<dim3(NN/32, BB), 256>>>(nodes, mask, nw, modes);
    fc0_kernel<<<(BB*CC*NN)/256, 256>>>(x, fc0w, fc0b, hh0, hl0);
    split_weights_kernel<<<(LL*CC*CC)/256, 256>>>(convw, fc1w);

    bf *ch = hh0, *cl = hl0, *oh = hh1, *ol = hl1;
    for (int l = 0; l < LL; l++) {
        trans_split<<<dim3(NN/32, 4*BB), 256>>>(ch, cl);
        gemm_fwd<<<dim3(NSPLIT, BB), 256>>>(ch, wbcp, pcp);
        gemm_fwd<<<dim3(NSPLIT, BB), 256>>>(ch, wbsp, psp);
        reduce_kernel<<<(BB*CC*KK)/256, 256>>>();
        x0_kernel<<<dim3(CC, BB), 256>>>(ch, nw, mask);
        f0_kernel<<<BB, CC>>>(w0, l);
        mix_kernel<<<dim3(CC, BB), KK>>>(wc, ws_, l);
        inv3<<<dim3(NN/128, BB), 256>>>(nch, ncl, oh, ol, convb, mask, l, (l != LL-1) ? 1 : 0);
        bf* t;
        t = ch; ch = oh; oh = t;
        t = cl; cl = ol; ol = t;
    }
    trans_split<<<dim3(NN/32, 4*BB), 256>>>(ch, cl);
    fc1_mma<<<dim3(NN/128, BB), 256>>>(nch, ncl, fc1b);
    fc2_kernel<<<dim3(NN/128, BB), 128>>>(f1p, out, fc2w, fc2b, mask);
}

// round 10
// speedup vs baseline: 2.1690x; 1.0312x over previous
#include <cuda_runtime.h>
#include <cuda_bf16.h>
#include <cstdint>
#include <math.h>

#define BB 8
#define NN 16384
#define KK 128
#define CC 128
#define LL 4
#define NSPLIT 32
#define XS (NN / NSPLIT)   // 512
#define PAD 40
#define TRS 132

typedef __nv_bfloat16 bf;

// ---------------- device scratch ----------------
__device__ bf g_bc[BB*NN*KK];                            // bases_c [b][n][k] bf16
__device__ bf g_bs[BB*NN*KK];                            // bases_s [b][n][k] bf16
__device__ bf g_wbc[BB*KK*NN];                           // (cos*mask*nw)^T [b][k][n] bf16
__device__ bf g_wbs[BB*KK*NN];
__device__ bf g_hcnh[2][BB*CC*NN], g_hcnl[2][BB*CC*NN]; // split h [b][c][n], double buffer
__device__ bf g_nch[BB*NN*CC], g_ncl[BB*NN*CC];         // split h [b][n][c]
__device__ float g_pc[NSPLIT*BB*CC*KK], g_ps[NSPLIT*BB*CC*KK];
__device__ float g_xc[BB*CC*KK], g_xs[BB*CC*KK];
__device__ float g_x0v[BB*CC], g_f0v[BB*CC];
__device__ bf g_fcw[BB*CC*KK];                           // 2*f_c_hat bf16
__device__ bf g_fsw[BB*CC*KK];                           // -2*f_s_hat bf16
__device__ bf g_cw_hi[LL*CC*CC], g_cw_lo[LL*CC*CC];     // conv_w split [l][o][i]
__device__ bf g_w1t_hi[CC*CC], g_w1t_lo[CC*CC];         // fc1_w^T split [j][c]

// ---------------- helpers ----------------
__device__ __forceinline__ void split_bf(float v, bf& h, bf& l) {
    h = __float2bfloat16(v);
    l = __float2bfloat16(v - __bfloat162float(h));
}
__device__ __forceinline__ float gelu_exact(float v) {
    return 0.5f * v * (1.0f + erff(v * 0.70710678118654752f));
}
#define MMA(d, a0, a1, a2, a3, b0, b1) \
    asm volatile("mma.sync.aligned.m16n8k16.row.col.f32.bf16.bf16.f32 " \
        "{%0,%1,%2,%3}, {%4,%5,%6,%7}, {%8,%9}, {%0,%1,%2,%3};" \
        : "+f"((d)[0]), "+f"((d)[1]), "+f"((d)[2]), "+f"((d)[3]) \
        : "r"(a0), "r"(a1), "r"(a2), "r"(a3), "r"(b0), "r"(b1))

__device__ __forceinline__ void cp_tile(bf* dst, const bf* __restrict__ src, size_t ldm, int tid) {
#pragma unroll
    for (int j = 0; j < 2; j++) {
        int idx = tid + j * 256;
        int row = idx >> 2, q = idx & 3;
        *(uint4*)(dst + row * PAD + q * 8) = *(const uint4*)(src + (size_t)row * ldm + q * 8);
    }
}

// single-term: acc += A*B (plain bf16, spectral path)
__device__ __forceinline__ void gemm_chunk1(const bf* A, const bf* B,
                                            float acc[4][4][4], int g, int tg, int m0, int n0) {
#pragma unroll
    for (int ks = 0; ks < 32; ks += 16) {
        uint32_t bh[4][2];
#pragma unroll
        for (int nt = 0; nt < 4; nt++) {
            const bf* p = B + (n0 + nt * 8 + g) * PAD + ks + tg * 2;
            bh[nt][0] = *(const uint32_t*)p;
            bh[nt][1] = *(const uint32_t*)(p + 8);
        }
#pragma unroll
        for (int mt = 0; mt < 4; mt++) {
            const bf* p = A + (m0 + mt * 16 + g) * PAD + ks + tg * 2;
            uint32_t a0 = *(const uint32_t*)p;
            uint32_t a1 = *(const uint32_t*)(p + 8 * PAD);
            uint32_t a2 = *(const uint32_t*)(p + 8);
            uint32_t a3 = *(const uint32_t*)(p + 8 * PAD + 8);
#pragma unroll
            for (int nt = 0; nt < 4; nt++)
                MMA(acc[mt][nt], a0, a1, a2, a3, bh[nt][0], bh[nt][1]);
        }
    }
}

// 3-term split: acc += Ah*Bh + Ah*Bl + Al*Bh (precision-critical path)
__device__ __forceinline__ void gemm_chunk3(const bf* Ah, const bf* Al, const bf* Bh, const bf* Bl,
                                            float acc[4][4][4], int g, int tg, int m0, int n0) {
#pragma unroll
    for (int ks = 0; ks < 32; ks += 16) {
        uint32_t bh[4][2], bl[4][2];
#pragma unroll
        for (int nt = 0; nt < 4; nt++) {
            const bf* p = Bh + (n0 + nt * 8 + g) * PAD + ks + tg * 2;
            bh[nt][0] = *(const uint32_t*)p;
            bh[nt][1] = *(const uint32_t*)(p + 8);
            const bf* q = Bl + (n0 + nt * 8 + g) * PAD + ks + tg * 2;
            bl[nt][0] = *(const uint32_t*)q;
            bl[nt][1] = *(const uint32_t*)(q + 8);
        }
#pragma unroll
        for (int mt = 0; mt < 4; mt++) {
            const bf* p = Ah + (m0 + mt * 16 + g) * PAD + ks + tg * 2;
            uint32_t ah0 = *(const uint32_t*)p;
            uint32_t ah1 = *(const uint32_t*)(p + 8 * PAD);
            uint32_t ah2 = *(const uint32_t*)(p + 8);
            uint32_t ah3 = *(const uint32_t*)(p + 8 * PAD + 8);
            const bf* q = Al + (m0 + mt * 16 + g) * PAD + ks + tg * 2;
            uint32_t al0 = *(const uint32_t*)q;
            uint32_t al1 = *(const uint32_t*)(q + 8 * PAD);
            uint32_t al2 = *(const uint32_t*)(q + 8);
            uint32_t al3 = *(const uint32_t*)(q + 8 * PAD + 8);
#pragma unroll
            for (int nt = 0; nt < 4; nt++) {
                MMA(acc[mt][nt], ah0, ah1, ah2, ah3, bh[nt][0], bh[nt][1]);
                MMA(acc[mt][nt], ah0, ah1, ah2, ah3, bl[nt][0], bl[nt][1]);
                MMA(acc[mt][nt], al0, al1, al2, al3, bh[nt][0], bh[nt][1]);
            }
        }
    }
}

// ---------------- producers ----------------
__global__ void bases_nk_kernel(const float* __restrict__ nodes, const float* __restrict__ mask,
                                const float* __restrict__ modes) {
    int gid = blockIdx.x * blockDim.x + threadIdx.x;
    int k = gid & (KK - 1);
    int bn = gid >> 7;
    float m = mask[bn];
    float t = nodes[bn*2] * __ldg(&modes[k*2]) + nodes[bn*2+1] * __ldg(&modes[k*2+1]);
    float s, c; sincosf(t, &s, &c);
    g_bc[gid] = __float2bfloat16(c * m);
    g_bs[gid] = __float2bfloat16(s * m);
}
__global__ void basesT_kernel(const float* __restrict__ nodes, const float* __restrict__ mask,
                              const float* __restrict__ nw, const float* __restrict__ modes) {
    __shared__ unsigned short Tc[KK*32], Tsn[KK*32];
    int n0 = blockIdx.x * 32, b = blockIdx.y, tid = threadIdx.x;
    for (int idx = tid; idx < KK*32; idx += 256) {
        int n = idx & 31, k = idx >> 5;
        int bn = b * NN + n0 + n;
        float f = mask[bn] * nw[bn];
        float t = nodes[bn*2] * __ldg(&modes[k*2]) + nodes[bn*2+1] * __ldg(&modes[k*2+1]);
        float s, c; sincosf(t, &s, &c);
        Tc[idx] = __bfloat16_as_ushort(__float2bfloat16(c * f));
        Tsn[idx] = __bfloat16_as_ushort(__float2bfloat16(s * f));
    }
    __syncthreads();
    for (int idx = tid; idx < KK*32; idx += 256) {
        int n = idx & 31, k = idx >> 5;
        size_t o = ((size_t)(b * KK + k)) * NN + n0 + n;
        g_wbc[o] = __ushort_as_bfloat16(Tc[idx]);
        g_wbs[o] = __ushort_as_bfloat16(Tsn[idx]);
    }
}
__global__ void fc0_kernel(const float* __restrict__ x, const float* __restrict__ w,
                           const float* __restrict__ bias,
                           bf* __restrict__ ohh, bf* __restrict__ ohl) {
    int gid = blockIdx.x * blockDim.x + threadIdx.x;   // (b,c,n), n fastest
    int n = gid & (NN-1), c = (gid >> 14) & (CC-1), b = gid >> 21;
    const float* xp = x + ((size_t)b*NN + n)*3;
    float v = bias[c] + xp[0]*w[c] + xp[1]*w[CC+c] + xp[2]*w[2*CC+c];
    bf hi, lo; split_bf(v, hi, lo);
    ohh[gid] = hi; ohl[gid] = lo;
}
__global__ void split_weights_kernel(const float* __restrict__ convw, const float* __restrict__ fc1w) {
    int gid = blockIdx.x * blockDim.x + threadIdx.x;   // LL*CC*CC
    bf h, l;
    split_bf(convw[gid], h, l);
    g_cw_hi[gid] = h; g_cw_lo[gid] = l;
    if (gid < CC*CC) {
        int j = gid >> 7, c = gid & 127;
        split_bf(fc1w[c*CC + j], h, l);   // transpose -> [j][c]
        g_w1t_hi[gid] = h; g_w1t_lo[gid] = l;
    }
}
// transpose: split hcn [b][c][n] -> split hnc [b][n][c]   (used ONCE for fc0's h)
__global__ void trans_split(const bf* __restrict__ hh, const bf* __restrict__ hl) {
    __shared__ uint32_t T[32][33];
    int n0 = blockIdx.x * 32;
    int cb = blockIdx.y & 3;
    int b = blockIdx.y >> 2;
    int c0 = cb * 32;
    int tx = threadIdx.x & 31, ty = threadIdx.x >> 5;   // 32 x 8
#pragma unroll
    for (int i = 0; i < 4; i++) {
        int c = c0 + ty + i * 8;
        size_t off = ((size_t)b * CC + c) * NN + n0 + tx;
        T[ty + i * 8][tx] = (uint32_t)__bfloat16_as_ushort(hh[off])
                          | ((uint32_t)__bfloat16_as_ushort(hl[off]) << 16);
    }
    __syncthreads();
#pragma unroll
    for (int i = 0; i < 4; i++) {
        int n = n0 + ty + i * 8;
        uint32_t v = T[tx][ty + i * 8];
        size_t o = ((size_t)b * NN + n) * CC + c0 + tx;
        g_nch[o] = __ushort_as_bfloat16((unsigned short)(v & 0xffff));
        g_ncl[o] = __ushort_as_bfloat16((unsigned short)(v >> 16));
    }
}

// ---------------- forward projection GEMM (bf16, spectral) ----------------
__global__ __launch_bounds__(256) void gemm_fwd(const bf* __restrict__ Ahg,
                                                const bf* __restrict__ Bhg,
                                                float* __restrict__ outp) {
    __shared__ bf As[128*PAD], Bs[128*PAD];
    int split = blockIdx.x, b = blockIdx.y;
    int tid = threadIdx.x, w = tid >> 5, lane = tid & 31, g = lane >> 2, tg = lane & 3;
    int m0 = (w & 1) * 64, n0 = (w >> 1) * 32;
    const bf* As_g = Ahg + (size_t)b * CC * NN;
    const bf* Bs_g = Bhg + (size_t)b * KK * NN;
    float acc[4][4][4];
#pragma unroll
    for (int i = 0; i < 4; i++)
#pragma unroll
        for (int j = 0; j < 4; j++)
#pragma unroll
            for (int q = 0; q < 4; q++) acc[i][j][q] = 0.f;

    for (int ch = 0; ch < XS / 32; ch++) {
        int x0 = split * XS + ch * 32;
        cp_tile(As, As_g + x0, NN, tid);
        cp_tile(Bs, Bs_g + x0, NN, tid);
        __syncthreads();
        gemm_chunk1(As, Bs, acc, g, tg, m0, n0);
        __syncthreads();
    }
    float* pp = outp + (size_t)(split * BB + b) * CC * KK;
#pragma unroll
    for (int mt = 0; mt < 4; mt++) {
        int r0 = m0 + mt * 16 + g;
#pragma unroll
        for (int nt = 0; nt < 4; nt++) {
            int n = n0 + nt * 8 + tg * 2;
            *(float2*)&pp[r0 * KK + n] = make_float2(acc[mt][nt][0], acc[mt][nt][1]);
            *(float2*)&pp[(r0 + 8) * KK + n] = make_float2(acc[mt][nt][2], acc[mt][nt][3]);
        }
    }
}

// ---------------- fused inverse: spectral (bf16) + conv (split); writes hcn AND hnc ----------------
__global__ __launch_bounds__(256) void inv3(const bf* __restrict__ hnc_hi, const bf* __restrict__ hnc_lo,
                                            bf* __restrict__ ohh, bf* __restrict__ ohl,
                                            bf* __restrict__ onch, bf* __restrict__ oncl,
                                            const float* __restrict__ convb,
                                            const float* __restrict__ mask,
                                            int l, int apply_gelu) {
    extern __shared__ char dyns[];
    bf* Ah = (bf*)dyns;
    bf* Al = Ah + 128 * PAD;
    bf* Bh = Al + 128 * PAD;
    bf* Bl = Bh + 128 * PAD;
    uint32_t* Tr = (uint32_t*)dyns;   // overlays tiles; used only after all MMA passes
    int xb = blockIdx.x * 128, b = blockIdx.y;
    int tid = threadIdx.x, w = tid >> 5, lane = tid & 31, g = lane >> 2, tg = lane & 3;
    int m0 = (w & 1) * 64, n0 = (w >> 1) * 32;
    float acc[4][4][4];
#pragma unroll
    for (int i = 0; i < 4; i++)
#pragma unroll
        for (int j = 0; j < 4; j++)
#pragma unroll
            for (int q = 0; q < 4; q++) acc[i][j][q] = 0.f;

    // pass 0/1: plain bf16 spectral
    for (int pass = 0; pass < 2; pass++) {
        const bf* pA = (pass ? g_fsw : g_fcw) + (size_t)b*CC*KK;
        const bf* pB = (pass ? g_bs : g_bc) + ((size_t)b*NN + xb)*KK;
        for (int ch = 0; ch < 4; ch++) {
            int k0 = ch * 32;
            cp_tile(Ah, pA + k0, 128, tid);
            cp_tile(Bh, pB + k0, 128, tid);
            __syncthreads();
            gemm_chunk1(Ah, Bh, acc, g, tg, m0, n0);
            __syncthreads();
        }
    }
    // pass 2: conv (3-term split)
    {
        const bf* pAh = g_cw_hi + (size_t)l*CC*CC;
        const bf* pAl = g_cw_lo + (size_t)l*CC*CC;
        const bf* pBh = hnc_hi + ((size_t)b*NN + xb)*CC;
        const bf* pBl = hnc_lo + ((size_t)b*NN + xb)*CC;
        for (int ch = 0; ch < 4; ch++) {
            int k0 = ch * 32;
            cp_tile(Ah, pAh + k0, 128, tid);
            cp_tile(Al, pAl + k0, 128, tid);
            cp_tile(Bh, pBh + k0, 128, tid);
            cp_tile(Bl, pBl + k0, 128, tid);
            __syncthreads();
            gemm_chunk3(Ah, Al, Bh, Bl, acc, g, tg, m0, n0);
            __syncthreads();
        }
    }
    // epilogue: add convb + f0*mask (+gelu), split; write hcn scattered + stage Tr for hnc
#pragma unroll
    for (int mt = 0; mt < 4; mt++) {
        int r0 = m0 + mt * 16 + g, r1 = r0 + 8;
        float cb0 = convb[l * CC + r0], f00 = g_f0v[b * CC + r0];
        float cb1 = convb[l * CC + r1], f01 = g_f0v[b * CC + r1];
#pragma unroll
        for (int nt = 0; nt < 4; nt++) {
            int n = n0 + nt * 8 + tg * 2;
            float mk0 = mask[(size_t)b * NN + xb + n];
            float mk1 = mask[(size_t)b * NN + xb + n + 1];
            float v00 = acc[mt][nt][0] + cb0 + f00 * mk0;
            float v01 = acc[mt][nt][1] + cb0 + f00 * mk1;
            float v10 = acc[mt][nt][2] + cb1 + f01 * mk0;
            float v11 = acc[mt][nt][3] + cb1 + f01 * mk1;
            if (apply_gelu) {
                v00 = gelu_exact(v00); v01 = gelu_exact(v01);
                v10 = gelu_exact(v10); v11 = gelu_exact(v11);
            }
            bf h00, l00, h01, l01, h10, l10, h11, l11;
            split_bf(v00, h00, l00); split_bf(v01, h01, l01);
            split_bf(v10, h10, l10); split_bf(v11, h11, l11);
            uint32_t p00 = (uint32_t)__bfloat16_as_ushort(h00) | ((uint32_t)__bfloat16_as_ushort(l00) << 16);
            uint32_t p01 = (uint32_t)__bfloat16_as_ushort(h01) | ((uint32_t)__bfloat16_as_ushort(l01) << 16);
            uint32_t p10 = (uint32_t)__bfloat16_as_ushort(h10) | ((uint32_t)__bfloat16_as_ushort(l10) << 16);
            uint32_t p11 = (uint32_t)__bfloat16_as_ushort(h11) | ((uint32_t)__bfloat16_as_ushort(l11) << 16);
            size_t o0 = ((size_t)b * CC + r0) * NN + xb + n;
            size_t o1 = ((size_t)b * CC + r1) * NN + xb + n;
            *(uint32_t*)(ohh + o0) = (uint32_t)__bfloat16_as_ushort(h00) | ((uint32_t)__bfloat16_as_ushort(h01) << 16);
            *(uint32_t*)(ohl + o0) = (uint32_t)__bfloat16_as_ushort(l00) | ((uint32_t)__bfloat16_as_ushort(l01) << 16);
            *(uint32_t*)(ohh + o1) = (uint32_t)__bfloat16_as_ushort(h10) | ((uint32_t)__bfloat16_as_ushort(h11) << 16);
            *(uint32_t*)(ohl + o1) = (uint32_t)__bfloat16_as_ushort(l10) | ((uint32_t)__bfloat16_as_ushort(l11) << 16);
            Tr[n * TRS + r0]       = p00;
            Tr[(n + 1) * TRS + r0] = p01;
            Tr[n * TRS + r1]       = p10;
            Tr[(n + 1) * TRS + r1] = p11;
        }
    }
    __syncthreads();
    // coalesced hnc write from Tr (each CTA overwrites exactly the hnc slice it read)
    {
        int xq = tid >> 1;
        int c0t = (tid & 1) * 64;
        size_t ob = ((size_t)b * NN + xb + xq) * CC + c0t;
#pragma unroll
        for (int q = 0; q < 8; q++) {
            __align__(16) unsigned short hh8[8], ll8[8];
#pragma unroll
            for (int c = 0; c < 8; c++) {
                uint32_t v = Tr[xq * TRS + c0t + q * 8 + c];
                hh8[c] = (unsigned short)(v & 0xffff);
                ll8[c] = (unsigned short)(v >> 16);
            }
            *(uint4*)(onch + ob + q * 8) = *(uint4*)hh8;
            *(uint4*)(oncl + ob + q * 8) = *(uint4*)ll8;
        }
    }
}

// ---------------- small kernels ----------------
__global__ void reduce_kernel() {
    int gid = blockIdx.x * blockDim.x + threadIdx.x;
    float sc = 0.f, ss = 0.f;
#pragma unroll
    for (int s = 0; s < NSPLIT; s++) {
        sc += g_pc[(size_t)s * BB * CC * KK + gid];
        ss += g_ps[(size_t)s * BB * CC * KK + gid];
    }
    g_xc[gid] = sc;
    g_xs[gid] = -ss;
}
__global__ void x0_kernel(const bf* __restrict__ hh,
                          const float* __restrict__ nw, const float* __restrict__ mask) {
    int i = blockIdx.x, b = blockIdx.y;
    const bf* rh = hh + ((size_t)b * CC + i) * NN;
    const float* nwb = nw + b * NN;
    const float* mb = mask + b * NN;
    float acc = 0.f;
    for (int x = threadIdx.x; x < NN; x += 256)
        acc += __bfloat162float(rh[x]) * nwb[x] * mb[x];
    __shared__ float red[256];
    red[threadIdx.x] = acc;
    __syncthreads();
    for (int s = 128; s > 0; s >>= 1) {
        if (threadIdx.x < s) red[threadIdx.x] += red[threadIdx.x + s];
        __syncthreads();
    }
    if (threadIdx.x == 0) g_x0v[b * CC + i] = red[0];
}
__global__ void f0_kernel(const float* __restrict__ w0, int l) {
    int b = blockIdx.x, o = threadIdx.x;
    __shared__ float xs[CC];
    xs[o] = g_x0v[b * CC + o];
    __syncthreads();
    const float* w = w0 + (size_t)l * CC * CC;
    float acc = 0.f;
#pragma unroll 8
    for (int i = 0; i < CC; i++) acc += xs[i] * w[i * CC + o];
    g_f0v[b * CC + o] = acc;
}
__global__ void mix_kernel(const float* __restrict__ wc, const float* __restrict__ ws, int l) {
    int o = blockIdx.x, b = blockIdx.y, k = threadIdx.x;
    const float* wcl = wc + (size_t)l * CC * CC * KK;
    const float* wsl = ws + (size_t)l * CC * CC * KK;
    float fcA = 0.f, fsA = 0.f;
#pragma unroll 4
    for (int i = 0; i < CC; i++) {
        float xc = g_xc[(b * CC + i) * KK + k];
        float xv = g_xs[(b * CC + i) * KK + k];
        float wcv = wcl[((size_t)i * CC + o) * KK + k];
        float wsv = wsl[((size_t)i * CC + o) * KK + k];
        fcA += xc * wcv - xv * wsv;
        fsA += xv * wcv + xc * wsv;
    }
    int idx = (b * CC + o) * KK + k;
    g_fcw[idx] = __float2bfloat16(2.0f * fcA);
    g_fsw[idx] = __float2bfloat16(-2.0f * fsA);
}

// ---------------- fused fc1 (MMA split) + fc2 + mask ----------------
__global__ __launch_bounds__(256) void fc1fc2(const bf* __restrict__ hnc_hi, const bf* __restrict__ hnc_lo,
                                              const float* __restrict__ b1,
                                              const float* __restrict__ w2,
                                              const float* __restrict__ b2,
                                              const float* __restrict__ mask,
                                              float* __restrict__ out) {
    extern __shared__ char dyns[];
    bf* Ah = (bf*)dyns;
    bf* Al = Ah + 128 * PAD;
    bf* Bh = Al + 128 * PAD;
    bf* Bl = Bh + 128 * PAD;
    float* Tsm = (float*)dyns;                   // overlay, 128*TRS floats (after MMA)
    float* w2s = (float*)(dyns + 128 * TRS * 4); // 128 floats, beyond tiles & Tsm
    float* part = w2s + 128;                     // 256 floats
    int xb = blockIdx.x * 128, b = blockIdx.y;
    int tid = threadIdx.x, w = tid >> 5, lane = tid & 31, g = lane >> 2, tg = lane & 3;
    int m0 = (w & 1) * 64, n0 = (w >> 1) * 32;
    if (tid < 128) w2s[tid] = w2[tid];
    const bf* pBh = hnc_hi + ((size_t)b * NN + xb) * CC;
    const bf* pBl = hnc_lo + ((size_t)b * NN + xb) * CC;
    float acc[4][4][4];
#pragma unroll
    for (int i = 0; i < 4; i++)
#pragma unroll
        for (int j = 0; j < 4; j++)
#pragma unroll
            for (int q = 0; q < 4; q++) acc[i][j][q] = 0.f;

    for (int ch = 0; ch < 4; ch++) {
        int k0 = ch * 32;
        cp_tile(Ah, g_w1t_hi + k0, 128, tid);
        cp_tile(Al, g_w1t_lo + k0, 128, tid);
        cp_tile(Bh, pBh + k0, 128, tid);
        cp_tile(Bl, pBl + k0, 128, tid);
        __syncthreads();
        gemm_chunk3(Ah, Al, Bh, Bl, acc, g, tg, m0, n0);
        __syncthreads();
    }
    // stage gelu(fc1) into Tsm[x][j]
#pragma unroll
    for (int mt = 0; mt < 4; mt++) {
        int r0 = m0 + mt * 16 + g, r1 = r0 + 8;
        float bb0 = b1[r0], bb8 = b1[r1];
#pragma unroll
        for (int nt = 0; nt < 4; nt++) {
            int n = n0 + nt * 8 + tg * 2;
            Tsm[n * TRS + r0]       = gelu_exact(acc[mt][nt][0] + bb0);
            Tsm[(n + 1) * TRS + r0] = gelu_exact(acc[mt][nt][1] + bb0);
            Tsm[n * TRS + r1]       = gelu_exact(acc[mt][nt][2] + bb8);
            Tsm[(n + 1) * TRS + r1] = gelu_exact(acc[mt][nt][3] + bb8);
        }
    }
    __syncthreads();
    // fc2: deterministic reduction over j
    {
        int xq = tid >> 1;
        int jh = (tid & 1) * 64;
        float p = 0.f;
#pragma unroll 8
        for (int j = 0; j < 64; j++)
            p += Tsm[xq * TRS + jh + j] * w2s[jh + j];
        part[tid] = p;
        __syncthreads();
        if ((tid & 1) == 0) {
            size_t xi = (size_t)b * NN + xb + xq;
            out[xi] = (part[tid] + part[tid + 1] + b2[0]) * mask[xi];
        }
    }
}

// ---------------- launch ----------------
extern "C" void kernel_launch(void* const* d_in, const int* in_sizes, int n_in,
                              void* d_out, int out_size) {
    const float* x     = (const float*)d_in[0];
    const float* nodes = (const float*)d_in[1];
    const float* mask  = (const float*)d_in[2];
    const float* nw    = (const float*)d_in[3];
    const float* modes = (const float*)d_in[4];
    const float* fc0w  = (const float*)d_in[5];
    const float* fc0b  = (const float*)d_in[6];
    const float* wc    = (const float*)d_in[7];
    const float* ws_   = (const float*)d_in[8];
    const float* w0    = (const float*)d_in[9];
    const float* convw = (const float*)d_in[10];
    const float* convb = (const float*)d_in[11];
    const float* fc1w  = (const float*)d_in[12];
    const float* fc1b  = (const float*)d_in[13];
    const float* fc2w  = (const float*)d_in[14];
    const float* fc2b  = (const float*)d_in[15];
    float* out = (float*)d_out;

    const int INV_SMEM = 128 * TRS * 4;              // 67584
    const int FC_SMEM  = 128 * TRS * 4 + (128 + 256) * 4;  // 69120
    cudaFuncSetAttribute(inv3, cudaFuncAttributeMaxDynamicSharedMemorySize, INV_SMEM);
    cudaFuncSetAttribute(fc1fc2, cudaFuncAttributeMaxDynamicSharedMemorySize, FC_SMEM);

    float *pcp, *psp;
    bf *wbcp, *wbsp, *nch, *ncl, *hh0, *hl0;
    cudaGetSymbolAddress((void**)&pcp, g_pc);
    cudaGetSymbolAddress((void**)&psp, g_ps);
    cudaGetSymbolAddress((void**)&wbcp, g_wbc);
    cudaGetSymbolAddress((void**)&wbsp, g_wbs);
    cudaGetSymbolAddress((void**)&nch, g_nch);
    cudaGetSymbolAddress((void**)&ncl, g_ncl);
    cudaGetSymbolAddress((void**)&hh0, g_hcnh);
    cudaGetSymbolAddress((void**)&hl0, g_hcnl);
    bf* hh1 = hh0 + (size_t)BB*CC*NN;
    bf* hl1 = hl0 + (size_t)BB*CC*NN;

    bases_nk_kernel<<<(BB*NN*KK)/256, 256>>>(nodes, mask, modes);
    basesT_kernel<<<dim3(NN/32, BB), 256>>>(nodes, mask, nw, modes);
    fc0_kernel<<<(BB*CC*NN)/256, 256>>>(x, fc0w, fc0b, hh0, hl0);
    split_weights_kernel<<<(LL*CC*CC)/256, 256>>>(convw, fc1w);
    trans_split<<<dim3(NN/32, 4*BB), 256>>>(hh0, hl0);   // initial hnc

    bf *ch = hh0, *cl = hl0, *oh = hh1, *ol = hl1;
    for (int l = 0; l < LL; l++) {
        gemm_fwd<<<dim3(NSPLIT, BB), 256>>>(ch, wbcp, pcp);
        gemm_fwd<<<dim3(NSPLIT, BB), 256>>>(ch, wbsp, psp);
        reduce_kernel<<<(BB*CC*KK)/256, 256>>>();
        x0_kernel<<<dim3(CC, BB), 256>>>(ch, nw, mask);
        f0_kernel<<<BB, CC>>>(w0, l);
        mix_kernel<<<dim3(CC, BB), KK>>>(wc, ws_, l);
        inv3<<<dim3(NN/128, BB), 256, INV_SMEM>>>(nch, ncl, oh, ol, nch, ncl,
                                                  convb, mask, l, (l != LL-1) ? 1 : 0);
        bf* t;
        t = ch; ch = oh; oh = t;
        t = cl; cl = ol; ol = t;
    }
    fc1fc2<<<dim3(NN/128, BB), 256, FC_SMEM>>>(nch, ncl, fc1b, fc2w, fc2b, mask, out);
}